// round 12
// baseline (speedup 1.0000x reference)
#include <cuda_runtime.h>
#include <cuda_fp16.h>
#include <cstdint>

#define L 2304
#define NBATCH 4
#define CIN 512
#define HCH 64
#define NH 8
#define NNH (NBATCH * NH)        // 32
#define NQT 18                   // q tiles of 128
#define NCHUNK 18                // key chunks of 128
#define NCB 288                  // column blocks of 8 over L
#define QKV_ELEMS (NBATCH * 192 * L)

// scratch (no cudaMalloc allowed)
__device__ float g_qkv[QKV_ELEMS];               // [n][192][L] fp32
__device__ float g_qp[2 * QKV_ELEMS];            // qkv K-split partials
__device__ float g_o[NBATCH * HCH * L];          // [n][64][L]
__device__ __half g_qh[NNH * L * 8];             // [nh][q][8]  (scaled)
__device__ __half g_kh[NNH * L * 8];             // [nh][k][8]
__device__ __half g_vh[NNH * 16 * L];            // [nh][dim16][k], plane8=ones
// split-f16 fragment images (hi/lo interleaved)
__device__ uint4 g_qwf[12 * 32 * 32 * 2];        // qkv_w A-frags {hi,lo}
__device__ uint4 g_rwf[32 * 4 * 32 * 2];         // res_w A-frags
__device__ uint4 g_xf[NBATCH * NCB * 32 * 32];   // x B-frags {bh0,bh1,bl0,bl1}
__device__ uint4 g_of[NBATCH * NCB * 4 * 32];    // attn-out B-frags

#define HMMA16(c0, c1, c2, c3, a0, a1, a2, a3, b0, b1) \
    asm volatile("mma.sync.aligned.m16n8k16.row.col.f32.f16.f16.f32 " \
        "{%0,%1,%2,%3}, {%4,%5,%6,%7}, {%8,%9}, {%0,%1,%2,%3};" \
        : "+f"(c0), "+f"(c1), "+f"(c2), "+f"(c3) \
        : "r"(a0), "r"(a1), "r"(a2), "r"(a3), "r"(b0), "r"(b1))

#define HMMA8(c0, c1, c2, c3, a0, a1, b0) \
    asm volatile("mma.sync.aligned.m16n8k8.row.col.f32.f16.f16.f32 " \
        "{%0,%1,%2,%3}, {%4,%5}, {%6}, {%0,%1,%2,%3};" \
        : "+f"(c0), "+f"(c1), "+f"(c2), "+f"(c3) \
        : "r"(a0), "r"(a1), "r"(b0))

__device__ __forceinline__ uint32_t split_pack(float a, float b, uint32_t& lo) {
    __half ha = __float2half_rn(a), hb = __float2half_rn(b);
    __half la = __float2half_rn(a - __half2float(ha));
    __half lb = __float2half_rn(b - __half2float(hb));
    lo = ((uint32_t)__half_as_ushort(lb) << 16) | __half_as_ushort(la);
    return ((uint32_t)__half_as_ushort(hb) << 16) | __half_as_ushort(ha);
}

// ============================================================
// A-fragment builder: src [M][K] fp32 -> {hi,lo} uint4 pairs.
// ============================================================
__global__ void __launch_bounds__(256) afrag_split_kernel(
    const float* __restrict__ src, uint4* __restrict__ dst,
    int K, int NKB, int total)
{
    int id = blockIdx.x * 256 + threadIdx.x;
    if (id >= total) return;
    int lane = id & 31;
    int kblk = (id >> 5) % NKB;
    int mb   = id / (32 * NKB);
    int row = mb * 16 + (lane >> 2);
    int w   = kblk * 8 + (lane & 3);
    const float* s0 = src + (size_t)row * K;
    const float* s1 = s0 + 8 * K;
    uint4 hi, lo;
    hi.x = split_pack(s0[2 * w],     s0[2 * w + 1], lo.x);
    hi.y = split_pack(s1[2 * w],     s1[2 * w + 1], lo.y);
    hi.z = split_pack(s0[2 * w + 8], s0[2 * w + 9], lo.z);
    hi.w = split_pack(s1[2 * w + 8], s1[2 * w + 9], lo.w);
    dst[id * 2]     = hi;
    dst[id * 2 + 1] = lo;
}

// ============================================================
// B-fragment builder: src [nb][Kch][L] -> uint4 {bh0,bh1,bl0,bl1}.
// ============================================================
__global__ void __launch_bounds__(256) bfrag_split_kernel(
    const float* __restrict__ src, uint4* __restrict__ dst,
    int Kch, int NKB, int total)
{
    int id = blockIdx.x * 256 + threadIdx.x;
    if (id >= total) return;
    int lane = id & 31;
    int kblk = (id >> 5) % NKB;
    int cb   = (id / (32 * NKB)) % NCB;
    int nb   = id / (32 * NKB * NCB);
    int col = cb * 8 + (lane >> 2);
    int w   = kblk * 8 + (lane & 3);
    const float* s = src + (size_t)nb * Kch * L + col;
    uint4 o;
    o.x = split_pack(s[(size_t)(2 * w) * L],     s[(size_t)(2 * w + 1) * L], o.z);
    o.y = split_pack(s[(size_t)(2 * w + 8) * L], s[(size_t)(2 * w + 9) * L], o.w);
    dst[id] = o;
}

// ============================================================
// Split-f16 HMMA GEMM, register-prefetched A and B, merged accum.
// C[nb][m][l] = sum_k A[m][k]*B[nb][k][l] (+bias on ky==0).
// K-split writes plain stores into per-ky partial planes (pstride).
// grid (18, MBT*ksplit, NBATCH), 256 thr = 8 warps (2 m16 x 4 cb4).
// ============================================================
__global__ void __launch_bounds__(256) hgemm_split_kernel(
    const uint4* __restrict__ Af, const uint4* __restrict__ Bf,
    const float* __restrict__ bias, float* __restrict__ C,
    int M, int NKB, int ksplit, size_t pstride)
{
    int t = threadIdx.x, wid = t >> 5, lane = t & 31;
    int mw = wid >> 2, nw = wid & 3;
    int mbt = blockIdx.y / ksplit;
    int ky  = blockIdx.y % ksplit;
    int mb  = mbt * 2 + mw;
    int cb0 = blockIdx.x * 16 + nw * 4;
    int nb  = blockIdx.z;
    int r = lane >> 2, cq = lane & 3;
    int kbN = NKB / ksplit;
    int kb0 = ky * kbN;

    const uint4* pa = Af + ((size_t)mb * NKB + kb0) * 64 + lane * 2;
    const size_t jstr = (size_t)NKB * 32;
    const uint4* pb = Bf + (((size_t)nb * NCB + cb0) * NKB + kb0) * 32 + lane;

    float acc[4][4];
#pragma unroll
    for (int j = 0; j < 4; j++)
#pragma unroll
        for (int i = 0; i < 4; i++) acc[j][i] = 0.f;

    uint4 nA0 = pa[0], nA1 = pa[1];
    uint4 nB[4];
#pragma unroll
    for (int j = 0; j < 4; j++) nB[j] = pb[j * jstr];

    for (int kb = 0; kb < kbN; kb++) {
        uint4 ah = nA0, al = nA1;
        uint4 cB[4];
#pragma unroll
        for (int j = 0; j < 4; j++) cB[j] = nB[j];
        if (kb + 1 < kbN) {
            pa += 64;
            pb += 32;
            nA0 = pa[0];
            nA1 = pa[1];
#pragma unroll
            for (int j = 0; j < 4; j++) nB[j] = pb[j * jstr];
        }
#pragma unroll
        for (int j = 0; j < 4; j++) {
            HMMA16(acc[j][0], acc[j][1], acc[j][2], acc[j][3],
                   ah.x, ah.y, ah.z, ah.w, cB[j].x, cB[j].y);
            HMMA16(acc[j][0], acc[j][1], acc[j][2], acc[j][3],
                   ah.x, ah.y, ah.z, ah.w, cB[j].z, cB[j].w);
            HMMA16(acc[j][0], acc[j][1], acc[j][2], acc[j][3],
                   al.x, al.y, al.z, al.w, cB[j].x, cB[j].y);
        }
    }

    int row0 = mb * 16 + r;
    float b0 = 0.f, b1 = 0.f;
    if (ky == 0) { b0 = bias[row0]; b1 = bias[row0 + 8]; }
    float* base0 = C + ky * pstride + ((size_t)nb * M + row0) * L;
    float* base1 = base0 + 8 * L;
#pragma unroll
    for (int j = 0; j < 4; j++) {
        int col = (cb0 + j) * 8 + cq * 2;
        *(float2*)(base0 + col) = make_float2(acc[j][0] + b0, acc[j][1] + b0);
        *(float2*)(base1 + col) = make_float2(acc[j][2] + b1, acc[j][3] + b1);
    }
}

// ============================================================
// Combine qkv K-split partials: g_qkv = p0 + p1 (vectorized).
// ============================================================
__global__ void __launch_bounds__(256) qkv_combine_kernel()
{
    int id = blockIdx.x * 256 + threadIdx.x;
    const float4* p0 = (const float4*)g_qp;
    const float4* p1 = (const float4*)(g_qp + QKV_ELEMS);
    float4 a = p0[id], b = p1[id];
    ((float4*)g_qkv)[id] = make_float4(a.x + b.x, a.y + b.y, a.z + b.z, a.w + b.w);
}

// ============================================================
// Convert fp32 qkv -> fp16 fragment-friendly images (attention).
// ============================================================
#define NT_Q (NNH * L)
#define NT_K (NNH * L)
#define NT_V (NNH * 16 * (L / 8))

__global__ void __launch_bounds__(256) convert_kernel()
{
    const float QS = 0.35355339059327373f * 1.4426950408889634f;
    int id = blockIdx.x * 256 + threadIdx.x;

    if (id < NT_Q) {
        int nh = id / L, q = id - nh * L;
        int n = nh >> 3, h = nh & 7;
        const float* src = g_qkv + ((size_t)n * 192 + h * 24) * L + q;
        uint32_t w[4];
#pragma unroll
        for (int j = 0; j < 4; j++) {
            __half2 h2 = __floats2half2_rn(src[(size_t)(2 * j) * L] * QS,
                                           src[(size_t)(2 * j + 1) * L] * QS);
            w[j] = *(uint32_t*)&h2;
        }
        ((uint4*)g_qh)[id] = make_uint4(w[0], w[1], w[2], w[3]);
        return;
    }
    id -= NT_Q;
    if (id < NT_K) {
        int nh = id / L, k = id - nh * L;
        int n = nh >> 3, h = nh & 7;
        const float* src = g_qkv + ((size_t)n * 192 + h * 24 + 8) * L + k;
        uint32_t w[4];
#pragma unroll
        for (int j = 0; j < 4; j++) {
            __half2 h2 = __floats2half2_rn(src[(size_t)(2 * j) * L],
                                           src[(size_t)(2 * j + 1) * L]);
            w[j] = *(uint32_t*)&h2;
        }
        ((uint4*)g_kh)[id] = make_uint4(w[0], w[1], w[2], w[3]);
        return;
    }
    id -= NT_K;
    if (id < NT_V) {
        int nh = id / (16 * (L / 8));
        int rem = id - nh * 16 * (L / 8);
        int dim = rem / (L / 8);
        int blk = rem - dim * (L / 8);
        uint4 out;
        if (dim < 8) {
            int n = nh >> 3, h = nh & 7;
            const float* src = g_qkv + ((size_t)n * 192 + h * 24 + 16 + dim) * L + blk * 8;
            float4 f0 = *(const float4*)src;
            float4 f1 = *(const float4*)(src + 4);
            __half2 a = __floats2half2_rn(f0.x, f0.y);
            __half2 b = __floats2half2_rn(f0.z, f0.w);
            __half2 c = __floats2half2_rn(f1.x, f1.y);
            __half2 d = __floats2half2_rn(f1.z, f1.w);
            out = make_uint4(*(uint32_t*)&a, *(uint32_t*)&b, *(uint32_t*)&c, *(uint32_t*)&d);
        } else if (dim == 8) {
            out = make_uint4(0x3C003C00u, 0x3C003C00u, 0x3C003C00u, 0x3C003C00u);
        } else {
            out = make_uint4(0, 0, 0, 0);
        }
        ((uint4*)g_vh)[(size_t)(nh * 16 + dim) * (L / 8) + blk] = out;
    }
}

// ============================================================
// Attention via HMMA (f16 in, f32 accum).
// ============================================================
__global__ void __launch_bounds__(256) attn_hmma_kernel()
{
    __shared__ uint32_t sK[2][512];
    __shared__ uint32_t sV[2][16 * 68];
    int t = threadIdx.x, wid = t >> 5, lane = t & 31;
    int bid = blockIdx.x;
    int qt = bid % NQT;
    int nh = bid / NQT;
    int r = lane >> 2, cq = lane & 3;

    const uint32_t* kg = (const uint32_t*)g_kh + (size_t)nh * L * 4;
    const uint32_t* vg = (const uint32_t*)g_vh + (size_t)nh * 16 * (L / 2);

    int q0 = qt * 128 + wid * 16;
    const uint32_t* qgp = (const uint32_t*)g_qh + (size_t)(nh * L + q0) * 4;
    uint32_t qa0 = qgp[r * 4 + cq];
    uint32_t qa1 = qgp[(r + 8) * 4 + cq];
    const uint32_t C15 = 0x4B804B80u;

    int pl = t >> 4, qw = t & 15;

    uint2 kreg = ((const uint2*)kg)[t];
    uint4 vreg = *(const uint4*)(vg + (size_t)pl * (L / 2) + qw * 4);
    ((uint2*)sK[0])[t] = kreg;
    *(uint4*)&sV[0][pl * 68 + qw * 4] = vreg;
    __syncthreads();

    float o0[4] = {0.f, 0.f, 0.f, 0.f};
    float o1[4] = {0.f, 0.f, 0.f, 0.f};

    for (int c = 0; c < NCHUNK; c++) {
        int cur = c & 1;
        if (c + 1 < NCHUNK) {
            kreg = ((const uint2*)(kg + (size_t)(c + 1) * 512))[t];
            vreg = *(const uint4*)(vg + (size_t)pl * (L / 2) + (c + 1) * 64 + qw * 4);
        }

        uint32_t pa[16], pb[16];
#pragma unroll
        for (int j = 0; j < 16; j++) {
            uint32_t kb = sK[cur][j * 32 + r * 4 + cq];
            float s0 = -9.f, s1 = -9.f, s2 = -9.f, s3 = -9.f;
            HMMA8(s0, s1, s2, s3, qa0, qa1, kb);
            uint32_t x, y;
            asm("cvt.rn.f16x2.f32 %0, %1, %2;" : "=r"(x) : "f"(s1), "f"(s0));
            asm("min.f16x2 %0, %0, %1;" : "+r"(x) : "r"(C15));
            asm("ex2.approx.f16x2 %0, %1;" : "=r"(x) : "r"(x));
            asm("cvt.rn.f16x2.f32 %0, %1, %2;" : "=r"(y) : "f"(s3), "f"(s2));
            asm("min.f16x2 %0, %0, %1;" : "+r"(y) : "r"(C15));
            asm("ex2.approx.f16x2 %0, %1;" : "=r"(y) : "r"(y));
            pa[j] = x;
            pb[j] = y;
        }

#pragma unroll
        for (int s = 0; s < 8; s++) {
            uint32_t b0 = sV[cur][r * 68 + s * 8 + cq];
            uint32_t b1 = sV[cur][r * 68 + s * 8 + cq + 4];
            HMMA16(o0[0], o0[1], o0[2], o0[3],
                   pa[2 * s], pb[2 * s], pa[2 * s + 1], pb[2 * s + 1], b0, b1);
            uint32_t b2 = sV[cur][(r + 8) * 68 + s * 8 + cq];
            uint32_t b3 = sV[cur][(r + 8) * 68 + s * 8 + cq + 4];
            HMMA16(o1[0], o1[1], o1[2], o1[3],
                   pa[2 * s], pb[2 * s], pa[2 * s + 1], pb[2 * s + 1], b2, b3);
        }

        if (c + 1 < NCHUNK) {
            int nxt = cur ^ 1;
            ((uint2*)sK[nxt])[t] = kreg;
            *(uint4*)&sV[nxt][pl * 68 + qw * 4] = vreg;
        }
        __syncthreads();
    }

    float ss_lo = __shfl_sync(0xffffffffu, o1[0], lane & ~3);
    float ss_hi = __shfl_sync(0xffffffffu, o1[2], lane & ~3);
    float inv_lo = 1.f / fmaxf(ss_lo, 1e-30f);
    float inv_hi = 1.f / fmaxf(ss_hi, 1e-30f);

    int n = nh >> 3, h = nh & 7;
    float* dst = g_o + ((size_t)n * HCH + h * 8 + cq * 2) * L + q0 + r;
    dst[0]     = o0[0] * inv_lo;
    dst[8]     = o0[2] * inv_hi;
    dst[L]     = o0[1] * inv_lo;
    dst[L + 8] = o0[3] * inv_hi;
}

// ============================================================
// Pos 3x3 conv as implicit GEMM over V, K-split 4x, atomicAdd merge.
// grid (72, 4, 4) = 1152 CTAs.
// ============================================================
__global__ void __launch_bounds__(256) pos_gemm_kernel(
    const float* __restrict__ pw, const float* __restrict__ pb)
{
    __shared__ float As[16][68];
    __shared__ float Bs[16][36];
    int n  = blockIdx.z;
    int ky = blockIdx.y;
    int l0 = blockIdx.x * 32;
    int t  = threadIdx.x;
    int tm = t >> 4, tn = t & 15;

    float acc[4][2];
#pragma unroll
    for (int i = 0; i < 4; i++) { acc[i][0] = 0.f; acc[i][1] = 0.f; }

    int kbase = ky * 144;
    for (int k0 = kbase; k0 < kbase + 144; k0 += 16) {
        {
            int m = t >> 2, kk = (t & 3) * 4;
            float4 a = *(const float4*)(pw + (size_t)m * 576 + k0 + kk);
            As[kk + 0][m] = a.x; As[kk + 1][m] = a.y;
            As[kk + 2][m] = a.z; As[kk + 3][m] = a.w;
        }
        {
#pragma unroll
            for (int u = 0; u < 2; u++) {
                int e = t * 2 + u;
                int kk = e >> 5, col = e & 31;
                int k = k0 + kk;
                int ic = k / 9;
                int tap = k - ic * 9;
                int dy = tap / 3 - 1, dx = tap - (tap / 3) * 3 - 1;
                int px = l0 + col;
                int y = px / 48, x = px - y * 48;
                int gy = y + dy, gx = x + dx;
                float v = 0.f;
                if ((unsigned)gy < 48u && (unsigned)gx < 48u) {
                    int c = (ic >> 3) * 24 + 16 + (ic & 7);
                    v = g_qkv[((size_t)n * 192 + c) * L + gy * 48 + gx];
                }
                Bs[kk][col] = v;
            }
        }
        __syncthreads();
#pragma unroll
        for (int kk = 0; kk < 16; kk++) {
            float4 a4 = *(const float4*)&As[kk][tm * 4];
            float2 b2 = *(const float2*)&Bs[kk][tn * 2];
            float ar[4] = {a4.x, a4.y, a4.z, a4.w};
#pragma unroll
            for (int i = 0; i < 4; i++) {
                acc[i][0] = fmaf(ar[i], b2.x, acc[i][0]);
                acc[i][1] = fmaf(ar[i], b2.y, acc[i][1]);
            }
        }
        __syncthreads();
    }

#pragma unroll
    for (int i = 0; i < 4; i++) {
        int m = tm * 4 + i;
        float bb = (ky == 0) ? pb[m] : 0.f;
        float* dst = g_o + ((size_t)n * HCH + m) * L + l0 + tn * 2;
        atomicAdd(dst,     acc[i][0] + bb);
        atomicAdd(dst + 1, acc[i][1] + bb);
    }
}

// ============================================================
extern "C" void kernel_launch(void* const* d_in, const int* in_sizes, int n_in,
                              void* d_out, int out_size)
{
    const float* x     = (const float*)d_in[0];
    const float* qkv_w = (const float*)d_in[1];
    const float* qkv_b = (const float*)d_in[2];
    const float* pos_w = (const float*)d_in[3];
    const float* pos_b = (const float*)d_in[4];
    const float* res_w = (const float*)d_in[5];
    const float* res_b = (const float*)d_in[6];
    float* out = (float*)d_out;

    float* qp_ptr = nullptr;
    cudaGetSymbolAddress((void**)&qp_ptr, g_qp);
    float* o_ptr = nullptr;
    cudaGetSymbolAddress((void**)&o_ptr, g_o);
    uint4 *qwf, *rwf, *xf, *of;
    cudaGetSymbolAddress((void**)&qwf, g_qwf);
    cudaGetSymbolAddress((void**)&rwf, g_rwf);
    cudaGetSymbolAddress((void**)&xf, g_xf);
    cudaGetSymbolAddress((void**)&of, g_of);

    // K1a: build A-frags for qkv_w [192x512] and res_w [512x64]
    afrag_split_kernel<<<48, 256>>>(qkv_w, qwf, 512, 32, 12 * 32 * 32);
    afrag_split_kernel<<<16, 256>>>(res_w, rwf, 64, 4, 32 * 4 * 32);
    // K1b: build B-frags for x
    {
        int total = NBATCH * NCB * 32 * 32;
        bfrag_split_kernel<<<(total + 255) / 256, 256>>>(x, xf, 512, 32, total);
    }
    // K1c: qkv GEMM (split-f16 HMMA, K-split 2x, plain partial stores)
    hgemm_split_kernel<<<dim3(18, 12, NBATCH), 256>>>(
        qwf, xf, qkv_b, qp_ptr, 192, 32, 2, (size_t)QKV_ELEMS);
    // K1d: combine partials -> g_qkv
    qkv_combine_kernel<<<QKV_ELEMS / 4 / 256, 256>>>();

    // K2: attention fragment images
    {
        int total = NT_Q + NT_K + NT_V;
        convert_kernel<<<(total + 255) / 256, 256>>>();
    }

    // K3: attention (HMMA tensor cores)
    attn_hmma_kernel<<<NNH * NQT, 256>>>();

    // K4: pos conv (K-split 4x, atomicAdd into g_o)
    pos_gemm_kernel<<<dim3(72, 4, NBATCH), 256>>>(pos_w, pos_b);

    // K5a: build B-frags for attention+pos output
    {
        int total = NBATCH * NCB * 4 * 32;
        bfrag_split_kernel<<<(total + 255) / 256, 256>>>(o_ptr, of, 64, 4, total);
    }
    // K5b: res GEMM (split-f16 HMMA) -> out
    hgemm_split_kernel<<<dim3(18, 16, NBATCH), 256>>>(
        rwf, of, res_b, out, 512, 4, 1, 0);
}

// round 13
// speedup vs baseline: 1.5301x; 1.5301x over previous
#include <cuda_runtime.h>
#include <cuda_fp16.h>
#include <cstdint>

#define L 2304
#define NBATCH 4
#define CIN 512
#define HCH 64
#define NH 8
#define NNH (NBATCH * NH)        // 32
#define NQT 18                   // q tiles of 128
#define NCHUNK 18                // key chunks of 128
#define NCB 288                  // column blocks of 8 over L

// scratch (no cudaMalloc allowed)
__device__ float g_qkv[NBATCH * 192 * L];        // [n][192][L] fp32
__device__ float g_o[NBATCH * HCH * L];          // [n][64][L]
__device__ __half g_qh[NNH * L * 8];             // [nh][q][8]  (scaled)
__device__ __half g_kh[NNH * L * 8];             // [nh][k][8]
__device__ __half g_vh[NNH * 16 * L];            // [nh][dim16][k], plane8=ones
// split-f16 fragment images (hi/lo interleaved)
__device__ uint4 g_qwf[12 * 32 * 32 * 2];        // qkv_w A-frags {hi,lo}
__device__ uint4 g_rwf[32 * 4 * 32 * 2];         // res_w A-frags
__device__ uint4 g_xf[NBATCH * NCB * 32 * 32];   // x B-frags {bh0,bh1,bl0,bl1}
__device__ uint4 g_of[NBATCH * NCB * 4 * 32];    // attn-out B-frags

#define HMMA16(c0, c1, c2, c3, a0, a1, a2, a3, b0, b1) \
    asm volatile("mma.sync.aligned.m16n8k16.row.col.f32.f16.f16.f32 " \
        "{%0,%1,%2,%3}, {%4,%5,%6,%7}, {%8,%9}, {%0,%1,%2,%3};" \
        : "+f"(c0), "+f"(c1), "+f"(c2), "+f"(c3) \
        : "r"(a0), "r"(a1), "r"(a2), "r"(a3), "r"(b0), "r"(b1))

#define HMMA8(c0, c1, c2, c3, a0, a1, b0) \
    asm volatile("mma.sync.aligned.m16n8k8.row.col.f32.f16.f16.f32 " \
        "{%0,%1,%2,%3}, {%4,%5}, {%6}, {%0,%1,%2,%3};" \
        : "+f"(c0), "+f"(c1), "+f"(c2), "+f"(c3) \
        : "r"(a0), "r"(a1), "r"(b0))

__device__ __forceinline__ uint32_t split_pack(float a, float b, uint32_t& lo) {
    __half ha = __float2half_rn(a), hb = __float2half_rn(b);
    __half la = __float2half_rn(a - __half2float(ha));
    __half lb = __float2half_rn(b - __half2float(hb));
    lo = ((uint32_t)__half_as_ushort(lb) << 16) | __half_as_ushort(la);
    return ((uint32_t)__half_as_ushort(hb) << 16) | __half_as_ushort(ha);
}

// ============================================================
// A-fragment builder: src [M][K] fp32 -> {hi,lo} uint4 pairs.
// ============================================================
__global__ void __launch_bounds__(256) afrag_split_kernel(
    const float* __restrict__ src, uint4* __restrict__ dst,
    int K, int NKB, int total)
{
    int id = blockIdx.x * 256 + threadIdx.x;
    if (id >= total) return;
    int lane = id & 31;
    int kblk = (id >> 5) % NKB;
    int mb   = id / (32 * NKB);
    int row = mb * 16 + (lane >> 2);
    int w   = kblk * 8 + (lane & 3);
    const float* s0 = src + (size_t)row * K;
    const float* s1 = s0 + 8 * K;
    uint4 hi, lo;
    hi.x = split_pack(s0[2 * w],     s0[2 * w + 1], lo.x);
    hi.y = split_pack(s1[2 * w],     s1[2 * w + 1], lo.y);
    hi.z = split_pack(s0[2 * w + 8], s0[2 * w + 9], lo.z);
    hi.w = split_pack(s1[2 * w + 8], s1[2 * w + 9], lo.w);
    dst[id * 2]     = hi;
    dst[id * 2 + 1] = lo;
}

// ============================================================
// B-fragment builder: src [nb][Kch][L] -> uint4 {bh0,bh1,bl0,bl1}.
// ============================================================
__global__ void __launch_bounds__(256) bfrag_split_kernel(
    const float* __restrict__ src, uint4* __restrict__ dst,
    int Kch, int NKB, int total)
{
    int id = blockIdx.x * 256 + threadIdx.x;
    if (id >= total) return;
    int lane = id & 31;
    int kblk = (id >> 5) % NKB;
    int cb   = (id / (32 * NKB)) % NCB;
    int nb   = id / (32 * NKB * NCB);
    int col = cb * 8 + (lane >> 2);
    int w   = kblk * 8 + (lane & 3);
    const float* s = src + (size_t)nb * Kch * L + col;
    uint4 o;
    o.x = split_pack(s[(size_t)(2 * w) * L],     s[(size_t)(2 * w + 1) * L], o.z);
    o.y = split_pack(s[(size_t)(2 * w + 8) * L], s[(size_t)(2 * w + 9) * L], o.w);
    dst[id] = o;
}

// ============================================================
// Split-f16 HMMA GEMM, register-prefetched B, merged accumulators.
// C[nb][m][l] = sum_k A[m][k]*B[nb][k][l] (+bias).
// addmode=1: atomicAdd into zeroed C, bias applied by ky==0.
// grid (18, MBT*ksplit, NBATCH), 256 thr = 8 warps (2 m16 x 4 cb4).
// ============================================================
__global__ void __launch_bounds__(256, 3) hgemm_split_kernel(
    const uint4* __restrict__ Af, const uint4* __restrict__ Bf,
    const float* __restrict__ bias, float* __restrict__ C,
    int M, int NKB, int ksplit, int addmode)
{
    int t = threadIdx.x, wid = t >> 5, lane = t & 31;
    int mw = wid >> 2, nw = wid & 3;
    int mbt = blockIdx.y / ksplit;
    int ky  = blockIdx.y % ksplit;
    int mb  = mbt * 2 + mw;
    int cb0 = blockIdx.x * 16 + nw * 4;
    int nb  = blockIdx.z;
    int r = lane >> 2, cq = lane & 3;
    int kbN = NKB / ksplit;
    int kb0 = ky * kbN;

    const uint4* pa = Af + ((size_t)mb * NKB + kb0) * 64 + lane * 2;
    const uint4* pb = Bf + (((size_t)nb * NCB + cb0) * NKB + kb0) * 32 + lane;

    float acc[4][4];
#pragma unroll
    for (int j = 0; j < 4; j++)
#pragma unroll
        for (int i = 0; i < 4; i++) acc[j][i] = 0.f;

    uint4 nB[4];
#pragma unroll
    for (int j = 0; j < 4; j++) nB[j] = pb[(size_t)j * NKB * 32];

    for (int kb = 0; kb < kbN; kb++) {
        uint4 cB[4];
#pragma unroll
        for (int j = 0; j < 4; j++) cB[j] = nB[j];
        if (kb + 1 < kbN) {
#pragma unroll
            for (int j = 0; j < 4; j++)
                nB[j] = pb[((size_t)j * NKB + kb + 1) * 32];
        }
        uint4 ah = pa[kb * 64];
        uint4 al = pa[kb * 64 + 1];
#pragma unroll
        for (int j = 0; j < 4; j++) {
            HMMA16(acc[j][0], acc[j][1], acc[j][2], acc[j][3],
                   ah.x, ah.y, ah.z, ah.w, cB[j].x, cB[j].y);
            HMMA16(acc[j][0], acc[j][1], acc[j][2], acc[j][3],
                   ah.x, ah.y, ah.z, ah.w, cB[j].z, cB[j].w);
            HMMA16(acc[j][0], acc[j][1], acc[j][2], acc[j][3],
                   al.x, al.y, al.z, al.w, cB[j].x, cB[j].y);
        }
    }

    int row0 = mb * 16 + r;
    float b0 = 0.f, b1 = 0.f;
    if (!addmode || ky == 0) { b0 = bias[row0]; b1 = bias[row0 + 8]; }
    float* base0 = C + ((size_t)nb * M + row0) * L;
    float* base1 = base0 + 8 * L;
#pragma unroll
    for (int j = 0; j < 4; j++) {
        int col = (cb0 + j) * 8 + cq * 2;
        float v00 = acc[j][0] + b0;
        float v01 = acc[j][1] + b0;
        float v10 = acc[j][2] + b1;
        float v11 = acc[j][3] + b1;
        if (addmode) {
            atomicAdd(base0 + col,     v00);
            atomicAdd(base0 + col + 1, v01);
            atomicAdd(base1 + col,     v10);
            atomicAdd(base1 + col + 1, v11);
        } else {
            *(float2*)(base0 + col) = make_float2(v00, v01);
            *(float2*)(base1 + col) = make_float2(v10, v11);
        }
    }
}

// ============================================================
// Convert fp32 qkv -> fp16 fragment-friendly images (attention).
// ============================================================
#define NT_Q (NNH * L)
#define NT_K (NNH * L)
#define NT_V (NNH * 16 * (L / 8))

__global__ void __launch_bounds__(256) convert_kernel()
{
    const float QS = 0.35355339059327373f * 1.4426950408889634f;
    int id = blockIdx.x * 256 + threadIdx.x;

    if (id < NT_Q) {
        int nh = id / L, q = id - nh * L;
        int n = nh >> 3, h = nh & 7;
        const float* src = g_qkv + ((size_t)n * 192 + h * 24) * L + q;
        uint32_t w[4];
#pragma unroll
        for (int j = 0; j < 4; j++) {
            __half2 h2 = __floats2half2_rn(src[(size_t)(2 * j) * L] * QS,
                                           src[(size_t)(2 * j + 1) * L] * QS);
            w[j] = *(uint32_t*)&h2;
        }
        ((uint4*)g_qh)[id] = make_uint4(w[0], w[1], w[2], w[3]);
        return;
    }
    id -= NT_Q;
    if (id < NT_K) {
        int nh = id / L, k = id - nh * L;
        int n = nh >> 3, h = nh & 7;
        const float* src = g_qkv + ((size_t)n * 192 + h * 24 + 8) * L + k;
        uint32_t w[4];
#pragma unroll
        for (int j = 0; j < 4; j++) {
            __half2 h2 = __floats2half2_rn(src[(size_t)(2 * j) * L],
                                           src[(size_t)(2 * j + 1) * L]);
            w[j] = *(uint32_t*)&h2;
        }
        ((uint4*)g_kh)[id] = make_uint4(w[0], w[1], w[2], w[3]);
        return;
    }
    id -= NT_K;
    if (id < NT_V) {
        int nh = id / (16 * (L / 8));
        int rem = id - nh * 16 * (L / 8);
        int dim = rem / (L / 8);
        int blk = rem - dim * (L / 8);
        uint4 out;
        if (dim < 8) {
            int n = nh >> 3, h = nh & 7;
            const float* src = g_qkv + ((size_t)n * 192 + h * 24 + 16 + dim) * L + blk * 8;
            float4 f0 = *(const float4*)src;
            float4 f1 = *(const float4*)(src + 4);
            __half2 a = __floats2half2_rn(f0.x, f0.y);
            __half2 b = __floats2half2_rn(f0.z, f0.w);
            __half2 c = __floats2half2_rn(f1.x, f1.y);
            __half2 d = __floats2half2_rn(f1.z, f1.w);
            out = make_uint4(*(uint32_t*)&a, *(uint32_t*)&b, *(uint32_t*)&c, *(uint32_t*)&d);
        } else if (dim == 8) {
            out = make_uint4(0x3C003C00u, 0x3C003C00u, 0x3C003C00u, 0x3C003C00u);
        } else {
            out = make_uint4(0, 0, 0, 0);
        }
        ((uint4*)g_vh)[(size_t)(nh * 16 + dim) * (L / 8) + blk] = out;
    }
}

// ============================================================
// Attention via HMMA (f16 in, f32 accum).
// ============================================================
__global__ void __launch_bounds__(256) attn_hmma_kernel()
{
    __shared__ uint32_t sK[2][512];
    __shared__ uint32_t sV[2][16 * 68];
    int t = threadIdx.x, wid = t >> 5, lane = t & 31;
    int bid = blockIdx.x;
    int qt = bid % NQT;
    int nh = bid / NQT;
    int r = lane >> 2, cq = lane & 3;

    const uint32_t* kg = (const uint32_t*)g_kh + (size_t)nh * L * 4;
    const uint32_t* vg = (const uint32_t*)g_vh + (size_t)nh * 16 * (L / 2);

    int q0 = qt * 128 + wid * 16;
    const uint32_t* qgp = (const uint32_t*)g_qh + (size_t)(nh * L + q0) * 4;
    uint32_t qa0 = qgp[r * 4 + cq];
    uint32_t qa1 = qgp[(r + 8) * 4 + cq];
    const uint32_t C15 = 0x4B804B80u;

    int pl = t >> 4, qw = t & 15;

    uint2 kreg = ((const uint2*)kg)[t];
    uint4 vreg = *(const uint4*)(vg + (size_t)pl * (L / 2) + qw * 4);
    ((uint2*)sK[0])[t] = kreg;
    *(uint4*)&sV[0][pl * 68 + qw * 4] = vreg;
    __syncthreads();

    float o0[4] = {0.f, 0.f, 0.f, 0.f};
    float o1[4] = {0.f, 0.f, 0.f, 0.f};

    for (int c = 0; c < NCHUNK; c++) {
        int cur = c & 1;
        if (c + 1 < NCHUNK) {
            kreg = ((const uint2*)(kg + (size_t)(c + 1) * 512))[t];
            vreg = *(const uint4*)(vg + (size_t)pl * (L / 2) + (c + 1) * 64 + qw * 4);
        }

        uint32_t pa[16], pb[16];
#pragma unroll
        for (int j = 0; j < 16; j++) {
            uint32_t kb = sK[cur][j * 32 + r * 4 + cq];
            float s0 = -9.f, s1 = -9.f, s2 = -9.f, s3 = -9.f;
            HMMA8(s0, s1, s2, s3, qa0, qa1, kb);
            uint32_t x, y;
            asm("cvt.rn.f16x2.f32 %0, %1, %2;" : "=r"(x) : "f"(s1), "f"(s0));
            asm("min.f16x2 %0, %0, %1;" : "+r"(x) : "r"(C15));
            asm("ex2.approx.f16x2 %0, %1;" : "=r"(x) : "r"(x));
            asm("cvt.rn.f16x2.f32 %0, %1, %2;" : "=r"(y) : "f"(s3), "f"(s2));
            asm("min.f16x2 %0, %0, %1;" : "+r"(y) : "r"(C15));
            asm("ex2.approx.f16x2 %0, %1;" : "=r"(y) : "r"(y));
            pa[j] = x;
            pb[j] = y;
        }

#pragma unroll
        for (int s = 0; s < 8; s++) {
            uint32_t b0 = sV[cur][r * 68 + s * 8 + cq];
            uint32_t b1 = sV[cur][r * 68 + s * 8 + cq + 4];
            HMMA16(o0[0], o0[1], o0[2], o0[3],
                   pa[2 * s], pb[2 * s], pa[2 * s + 1], pb[2 * s + 1], b0, b1);
            uint32_t b2 = sV[cur][(r + 8) * 68 + s * 8 + cq];
            uint32_t b3 = sV[cur][(r + 8) * 68 + s * 8 + cq + 4];
            HMMA16(o1[0], o1[1], o1[2], o1[3],
                   pa[2 * s], pb[2 * s], pa[2 * s + 1], pb[2 * s + 1], b2, b3);
        }

        if (c + 1 < NCHUNK) {
            int nxt = cur ^ 1;
            ((uint2*)sK[nxt])[t] = kreg;
            *(uint4*)&sV[nxt][pl * 68 + qw * 4] = vreg;
        }
        __syncthreads();
    }

    float ss_lo = __shfl_sync(0xffffffffu, o1[0], lane & ~3);
    float ss_hi = __shfl_sync(0xffffffffu, o1[2], lane & ~3);
    float inv_lo = 1.f / fmaxf(ss_lo, 1e-30f);
    float inv_hi = 1.f / fmaxf(ss_hi, 1e-30f);

    int n = nh >> 3, h = nh & 7;
    float* dst = g_o + ((size_t)n * HCH + h * 8 + cq * 2) * L + q0 + r;
    dst[0]     = o0[0] * inv_lo;
    dst[8]     = o0[2] * inv_hi;
    dst[L]     = o0[1] * inv_lo;
    dst[L + 8] = o0[3] * inv_hi;
}

// ============================================================
// Pos 3x3 conv as implicit GEMM over V, K-split 4x, atomicAdd merge.
// grid (72, 4, 4) = 1152 CTAs.
// ============================================================
__global__ void __launch_bounds__(256) pos_gemm_kernel(
    const float* __restrict__ pw, const float* __restrict__ pb)
{
    __shared__ float As[16][68];
    __shared__ float Bs[16][36];
    int n  = blockIdx.z;
    int ky = blockIdx.y;
    int l0 = blockIdx.x * 32;
    int t  = threadIdx.x;
    int tm = t >> 4, tn = t & 15;

    float acc[4][2];
#pragma unroll
    for (int i = 0; i < 4; i++) { acc[i][0] = 0.f; acc[i][1] = 0.f; }

    int kbase = ky * 144;
    for (int k0 = kbase; k0 < kbase + 144; k0 += 16) {
        {
            int m = t >> 2, kk = (t & 3) * 4;
            float4 a = *(const float4*)(pw + (size_t)m * 576 + k0 + kk);
            As[kk + 0][m] = a.x; As[kk + 1][m] = a.y;
            As[kk + 2][m] = a.z; As[kk + 3][m] = a.w;
        }
        {
#pragma unroll
            for (int u = 0; u < 2; u++) {
                int e = t * 2 + u;
                int kk = e >> 5, col = e & 31;
                int k = k0 + kk;
                int ic = k / 9;
                int tap = k - ic * 9;
                int dy = tap / 3 - 1, dx = tap - (tap / 3) * 3 - 1;
                int px = l0 + col;
                int y = px / 48, x = px - y * 48;
                int gy = y + dy, gx = x + dx;
                float v = 0.f;
                if ((unsigned)gy < 48u && (unsigned)gx < 48u) {
                    int c = (ic >> 3) * 24 + 16 + (ic & 7);
                    v = g_qkv[((size_t)n * 192 + c) * L + gy * 48 + gx];
                }
                Bs[kk][col] = v;
            }
        }
        __syncthreads();
#pragma unroll
        for (int kk = 0; kk < 16; kk++) {
            float4 a4 = *(const float4*)&As[kk][tm * 4];
            float2 b2 = *(const float2*)&Bs[kk][tn * 2];
            float ar[4] = {a4.x, a4.y, a4.z, a4.w};
#pragma unroll
            for (int i = 0; i < 4; i++) {
                acc[i][0] = fmaf(ar[i], b2.x, acc[i][0]);
                acc[i][1] = fmaf(ar[i], b2.y, acc[i][1]);
            }
        }
        __syncthreads();
    }

#pragma unroll
    for (int i = 0; i < 4; i++) {
        int m = tm * 4 + i;
        float bb = (ky == 0) ? pb[m] : 0.f;
        float* dst = g_o + ((size_t)n * HCH + m) * L + l0 + tn * 2;
        atomicAdd(dst,     acc[i][0] + bb);
        atomicAdd(dst + 1, acc[i][1] + bb);
    }
}

// ============================================================
extern "C" void kernel_launch(void* const* d_in, const int* in_sizes, int n_in,
                              void* d_out, int out_size)
{
    const float* x     = (const float*)d_in[0];
    const float* qkv_w = (const float*)d_in[1];
    const float* qkv_b = (const float*)d_in[2];
    const float* pos_w = (const float*)d_in[3];
    const float* pos_b = (const float*)d_in[4];
    const float* res_w = (const float*)d_in[5];
    const float* res_b = (const float*)d_in[6];
    float* out = (float*)d_out;

    float* qkv_ptr = nullptr;
    float* o_ptr   = nullptr;
    cudaGetSymbolAddress((void**)&qkv_ptr, g_qkv);
    cudaGetSymbolAddress((void**)&o_ptr, g_o);
    uint4 *qwf, *rwf, *xf, *of;
    cudaGetSymbolAddress((void**)&qwf, g_qwf);
    cudaGetSymbolAddress((void**)&rwf, g_rwf);
    cudaGetSymbolAddress((void**)&xf, g_xf);
    cudaGetSymbolAddress((void**)&of, g_of);

    // K0: zero g_qkv (atomicAdd target for K-split qkv GEMM)
    cudaMemsetAsync(qkv_ptr, 0, (size_t)NBATCH * 192 * L * sizeof(float));

    // K1a: build A-frags for qkv_w [192x512] and res_w [512x64]
    afrag_split_kernel<<<48, 256>>>(qkv_w, qwf, 512, 32, 12 * 32 * 32);
    afrag_split_kernel<<<16, 256>>>(res_w, rwf, 64, 4, 32 * 4 * 32);
    // K1b: build B-frags for x
    {
        int total = NBATCH * NCB * 32 * 32;
        bfrag_split_kernel<<<(total + 255) / 256, 256>>>(x, xf, 512, 32, total);
    }
    // K1c: qkv GEMM (split-f16 HMMA, K-split 2x, atomicAdd) -> g_qkv
    hgemm_split_kernel<<<dim3(18, 12, NBATCH), 256>>>(
        qwf, xf, qkv_b, qkv_ptr, 192, 32, 2, 1);

    // K2: attention fragment images
    {
        int total = NT_Q + NT_K + NT_V;
        convert_kernel<<<(total + 255) / 256, 256>>>();
    }

    // K3: attention (HMMA tensor cores)
    attn_hmma_kernel<<<NNH * NQT, 256>>>();

    // K4: pos conv (K-split 4x, atomicAdd into g_o)
    pos_gemm_kernel<<<dim3(72, 4, NBATCH), 256>>>(pos_w, pos_b);

    // K5a: build B-frags for attention+pos output
    {
        int total = NBATCH * NCB * 4 * 32;
        bfrag_split_kernel<<<(total + 255) / 256, 256>>>(o_ptr, of, 64, 4, total);
    }
    // K5b: res GEMM (split-f16 HMMA) -> out
    hgemm_split_kernel<<<dim3(18, 16, NBATCH), 256>>>(
        rwf, of, res_b, out, 512, 4, 1, 0);
}

// round 14
// speedup vs baseline: 1.5841x; 1.0353x over previous
#include <cuda_runtime.h>
#include <cuda_fp16.h>
#include <cstdint>

#define L 2304
#define NBATCH 4
#define CIN 512
#define HCH 64
#define NH 8
#define NNH (NBATCH * NH)        // 32
#define NQT 18                   // q tiles of 128
#define NCHUNK 18                // key chunks of 128
#define NCB 288                  // column blocks of 8 over L

// scratch (no cudaMalloc allowed)
__device__ float g_qkv[NBATCH * 192 * L];        // [n][192][L] fp32
__device__ float g_o[NBATCH * HCH * L];          // [n][64][L]
__device__ __half g_qh[NNH * L * 8];             // [nh][q][8]  (scaled)
__device__ __half g_kh[NNH * L * 8];             // [nh][k][8]
__device__ __half g_vh[NNH * 16 * L];            // [nh][dim16][k], plane8=ones
// split-f16 fragment images (hi/lo interleaved)
__device__ uint4 g_qwf[12 * 32 * 32 * 2];        // qkv_w A-frags {hi,lo}
__device__ uint4 g_rwf[32 * 4 * 32 * 2];         // res_w A-frags
__device__ uint4 g_xf[NBATCH * NCB * 32 * 32];   // x B-frags {bh0,bh1,bl0,bl1}
__device__ uint4 g_of[NBATCH * NCB * 4 * 32];    // attn-out B-frags

#define HMMA16(c0, c1, c2, c3, a0, a1, a2, a3, b0, b1) \
    asm volatile("mma.sync.aligned.m16n8k16.row.col.f32.f16.f16.f32 " \
        "{%0,%1,%2,%3}, {%4,%5,%6,%7}, {%8,%9}, {%0,%1,%2,%3};" \
        : "+f"(c0), "+f"(c1), "+f"(c2), "+f"(c3) \
        : "r"(a0), "r"(a1), "r"(a2), "r"(a3), "r"(b0), "r"(b1))

#define HMMA8(c0, c1, c2, c3, a0, a1, b0) \
    asm volatile("mma.sync.aligned.m16n8k8.row.col.f32.f16.f16.f32 " \
        "{%0,%1,%2,%3}, {%4,%5}, {%6}, {%0,%1,%2,%3};" \
        : "+f"(c0), "+f"(c1), "+f"(c2), "+f"(c3) \
        : "r"(a0), "r"(a1), "r"(b0))

__device__ __forceinline__ uint32_t split_pack(float a, float b, uint32_t& lo) {
    __half ha = __float2half_rn(a), hb = __float2half_rn(b);
    __half la = __float2half_rn(a - __half2float(ha));
    __half lb = __float2half_rn(b - __half2float(hb));
    lo = ((uint32_t)__half_as_ushort(lb) << 16) | __half_as_ushort(la);
    return ((uint32_t)__half_as_ushort(hb) << 16) | __half_as_ushort(ha);
}

// ============================================================
// A-fragment builder: src [M][K] fp32 -> {hi,lo} uint4 pairs.
// ============================================================
__global__ void __launch_bounds__(256) afrag_split_kernel(
    const float* __restrict__ src, uint4* __restrict__ dst,
    int K, int NKB, int total)
{
    int id = blockIdx.x * 256 + threadIdx.x;
    if (id >= total) return;
    int lane = id & 31;
    int kblk = (id >> 5) % NKB;
    int mb   = id / (32 * NKB);
    int row = mb * 16 + (lane >> 2);
    int w   = kblk * 8 + (lane & 3);
    const float* s0 = src + (size_t)row * K;
    const float* s1 = s0 + 8 * K;
    uint4 hi, lo;
    hi.x = split_pack(s0[2 * w],     s0[2 * w + 1], lo.x);
    hi.y = split_pack(s1[2 * w],     s1[2 * w + 1], lo.y);
    hi.z = split_pack(s0[2 * w + 8], s0[2 * w + 9], lo.z);
    hi.w = split_pack(s1[2 * w + 8], s1[2 * w + 9], lo.w);
    dst[id * 2]     = hi;
    dst[id * 2 + 1] = lo;
}

// ============================================================
// B-fragment builder: src [nb][Kch][L] -> uint4 {bh0,bh1,bl0,bl1}.
// ============================================================
__global__ void __launch_bounds__(256) bfrag_split_kernel(
    const float* __restrict__ src, uint4* __restrict__ dst,
    int Kch, int NKB, int total)
{
    int id = blockIdx.x * 256 + threadIdx.x;
    if (id >= total) return;
    int lane = id & 31;
    int kblk = (id >> 5) % NKB;
    int cb   = (id / (32 * NKB)) % NCB;
    int nb   = id / (32 * NKB * NCB);
    int col = cb * 8 + (lane >> 2);
    int w   = kblk * 8 + (lane & 3);
    const float* s = src + (size_t)nb * Kch * L + col;
    uint4 o;
    o.x = split_pack(s[(size_t)(2 * w) * L],     s[(size_t)(2 * w + 1) * L], o.z);
    o.y = split_pack(s[(size_t)(2 * w + 8) * L], s[(size_t)(2 * w + 9) * L], o.w);
    dst[id] = o;
}

// ============================================================
// Split-f16 HMMA GEMM, templated NKB/ksplit (immediate offsets,
// pointer-increment addressing), 4m x 2n warp layout.
// C[nb][m][l] = sum_k A[m][k]*B[nb][k][l] (+bias).
// ADDMODE=1: atomicAdd into zeroed C, bias applied by ky==0.
// grid (36, MBT*KSPLIT, NBATCH), 256 thr = 8 warps (4 m16 x 2 cb4).
// ============================================================
template <int NKB, int KSPLIT, int ADDMODE>
__global__ void __launch_bounds__(256, 3) hgemm_split_kernel(
    const uint4* __restrict__ Af, const uint4* __restrict__ Bf,
    const float* __restrict__ bias, float* __restrict__ C,
    int M)
{
    constexpr int kbN = NKB / KSPLIT;
    int t = threadIdx.x, wid = t >> 5, lane = t & 31;
    int mw = wid >> 1, nw = wid & 1;
    int mbt = blockIdx.y / KSPLIT;
    int ky  = blockIdx.y % KSPLIT;
    int mb  = mbt * 4 + mw;
    int cb0 = blockIdx.x * 8 + nw * 4;
    int nb  = blockIdx.z;
    int r = lane >> 2, cq = lane & 3;
    int kb0 = ky * kbN;

    const uint4* pa = Af + ((size_t)mb * NKB + kb0) * 64 + lane * 2;
    const uint4* pb = Bf + (((size_t)nb * NCB + cb0) * NKB + kb0) * 32 + lane;

    float acc[4][4];
#pragma unroll
    for (int j = 0; j < 4; j++)
#pragma unroll
        for (int i = 0; i < 4; i++) acc[j][i] = 0.f;

    uint4 nB[4];
#pragma unroll
    for (int j = 0; j < 4; j++) nB[j] = pb[j * (NKB * 32)];

#pragma unroll 4
    for (int kb = 0; kb < kbN; kb++) {
        uint4 cB[4];
#pragma unroll
        for (int j = 0; j < 4; j++) cB[j] = nB[j];
        uint4 ah = pa[0];
        uint4 al = pa[1];
        if (kb + 1 < kbN) {
            pb += 32;
            pa += 64;
#pragma unroll
            for (int j = 0; j < 4; j++) nB[j] = pb[j * (NKB * 32)];
        }
#pragma unroll
        for (int j = 0; j < 4; j++) {
            HMMA16(acc[j][0], acc[j][1], acc[j][2], acc[j][3],
                   ah.x, ah.y, ah.z, ah.w, cB[j].x, cB[j].y);
            HMMA16(acc[j][0], acc[j][1], acc[j][2], acc[j][3],
                   ah.x, ah.y, ah.z, ah.w, cB[j].z, cB[j].w);
            HMMA16(acc[j][0], acc[j][1], acc[j][2], acc[j][3],
                   al.x, al.y, al.z, al.w, cB[j].x, cB[j].y);
        }
    }

    int row0 = mb * 16 + r;
    float b0 = 0.f, b1 = 0.f;
    if (!ADDMODE || ky == 0) { b0 = bias[row0]; b1 = bias[row0 + 8]; }
    float* base0 = C + ((size_t)nb * M + row0) * L;
    float* base1 = base0 + 8 * L;
#pragma unroll
    for (int j = 0; j < 4; j++) {
        int col = (cb0 + j) * 8 + cq * 2;
        float v00 = acc[j][0] + b0;
        float v01 = acc[j][1] + b0;
        float v10 = acc[j][2] + b1;
        float v11 = acc[j][3] + b1;
        if (ADDMODE) {
            atomicAdd(base0 + col,     v00);
            atomicAdd(base0 + col + 1, v01);
            atomicAdd(base1 + col,     v10);
            atomicAdd(base1 + col + 1, v11);
        } else {
            *(float2*)(base0 + col) = make_float2(v00, v01);
            *(float2*)(base1 + col) = make_float2(v10, v11);
        }
    }
}

// ============================================================
// Convert fp32 qkv -> fp16 fragment-friendly images (attention).
// ============================================================
#define NT_Q (NNH * L)
#define NT_K (NNH * L)
#define NT_V (NNH * 16 * (L / 8))

__global__ void __launch_bounds__(256) convert_kernel()
{
    const float QS = 0.35355339059327373f * 1.4426950408889634f;
    int id = blockIdx.x * 256 + threadIdx.x;

    if (id < NT_Q) {
        int nh = id / L, q = id - nh * L;
        int n = nh >> 3, h = nh & 7;
        const float* src = g_qkv + ((size_t)n * 192 + h * 24) * L + q;
        uint32_t w[4];
#pragma unroll
        for (int j = 0; j < 4; j++) {
            __half2 h2 = __floats2half2_rn(src[(size_t)(2 * j) * L] * QS,
                                           src[(size_t)(2 * j + 1) * L] * QS);
            w[j] = *(uint32_t*)&h2;
        }
        ((uint4*)g_qh)[id] = make_uint4(w[0], w[1], w[2], w[3]);
        return;
    }
    id -= NT_Q;
    if (id < NT_K) {
        int nh = id / L, k = id - nh * L;
        int n = nh >> 3, h = nh & 7;
        const float* src = g_qkv + ((size_t)n * 192 + h * 24 + 8) * L + k;
        uint32_t w[4];
#pragma unroll
        for (int j = 0; j < 4; j++) {
            __half2 h2 = __floats2half2_rn(src[(size_t)(2 * j) * L],
                                           src[(size_t)(2 * j + 1) * L]);
            w[j] = *(uint32_t*)&h2;
        }
        ((uint4*)g_kh)[id] = make_uint4(w[0], w[1], w[2], w[3]);
        return;
    }
    id -= NT_K;
    if (id < NT_V) {
        int nh = id / (16 * (L / 8));
        int rem = id - nh * 16 * (L / 8);
        int dim = rem / (L / 8);
        int blk = rem - dim * (L / 8);
        uint4 out;
        if (dim < 8) {
            int n = nh >> 3, h = nh & 7;
            const float* src = g_qkv + ((size_t)n * 192 + h * 24 + 16 + dim) * L + blk * 8;
            float4 f0 = *(const float4*)src;
            float4 f1 = *(const float4*)(src + 4);
            __half2 a = __floats2half2_rn(f0.x, f0.y);
            __half2 b = __floats2half2_rn(f0.z, f0.w);
            __half2 c = __floats2half2_rn(f1.x, f1.y);
            __half2 d = __floats2half2_rn(f1.z, f1.w);
            out = make_uint4(*(uint32_t*)&a, *(uint32_t*)&b, *(uint32_t*)&c, *(uint32_t*)&d);
        } else if (dim == 8) {
            out = make_uint4(0x3C003C00u, 0x3C003C00u, 0x3C003C00u, 0x3C003C00u);
        } else {
            out = make_uint4(0, 0, 0, 0);
        }
        ((uint4*)g_vh)[(size_t)(nh * 16 + dim) * (L / 8) + blk] = out;
    }
}

// ============================================================
// Attention via HMMA (f16 in, f32 accum).
// ============================================================
__global__ void __launch_bounds__(256) attn_hmma_kernel()
{
    __shared__ uint32_t sK[2][512];
    __shared__ uint32_t sV[2][16 * 68];
    int t = threadIdx.x, wid = t >> 5, lane = t & 31;
    int bid = blockIdx.x;
    int qt = bid % NQT;
    int nh = bid / NQT;
    int r = lane >> 2, cq = lane & 3;

    const uint32_t* kg = (const uint32_t*)g_kh + (size_t)nh * L * 4;
    const uint32_t* vg = (const uint32_t*)g_vh + (size_t)nh * 16 * (L / 2);

    int q0 = qt * 128 + wid * 16;
    const uint32_t* qgp = (const uint32_t*)g_qh + (size_t)(nh * L + q0) * 4;
    uint32_t qa0 = qgp[r * 4 + cq];
    uint32_t qa1 = qgp[(r + 8) * 4 + cq];
    const uint32_t C15 = 0x4B804B80u;

    int pl = t >> 4, qw = t & 15;

    uint2 kreg = ((const uint2*)kg)[t];
    uint4 vreg = *(const uint4*)(vg + (size_t)pl * (L / 2) + qw * 4);
    ((uint2*)sK[0])[t] = kreg;
    *(uint4*)&sV[0][pl * 68 + qw * 4] = vreg;
    __syncthreads();

    float o0[4] = {0.f, 0.f, 0.f, 0.f};
    float o1[4] = {0.f, 0.f, 0.f, 0.f};

    for (int c = 0; c < NCHUNK; c++) {
        int cur = c & 1;
        if (c + 1 < NCHUNK) {
            kreg = ((const uint2*)(kg + (size_t)(c + 1) * 512))[t];
            vreg = *(const uint4*)(vg + (size_t)pl * (L / 2) + (c + 1) * 64 + qw * 4);
        }

        uint32_t pa[16], pb[16];
#pragma unroll
        for (int j = 0; j < 16; j++) {
            uint32_t kb = sK[cur][j * 32 + r * 4 + cq];
            float s0 = -9.f, s1 = -9.f, s2 = -9.f, s3 = -9.f;
            HMMA8(s0, s1, s2, s3, qa0, qa1, kb);
            uint32_t x, y;
            asm("cvt.rn.f16x2.f32 %0, %1, %2;" : "=r"(x) : "f"(s1), "f"(s0));
            asm("min.f16x2 %0, %0, %1;" : "+r"(x) : "r"(C15));
            asm("ex2.approx.f16x2 %0, %1;" : "=r"(x) : "r"(x));
            asm("cvt.rn.f16x2.f32 %0, %1, %2;" : "=r"(y) : "f"(s3), "f"(s2));
            asm("min.f16x2 %0, %0, %1;" : "+r"(y) : "r"(C15));
            asm("ex2.approx.f16x2 %0, %1;" : "=r"(y) : "r"(y));
            pa[j] = x;
            pb[j] = y;
        }

#pragma unroll
        for (int s = 0; s < 8; s++) {
            uint32_t b0 = sV[cur][r * 68 + s * 8 + cq];
            uint32_t b1 = sV[cur][r * 68 + s * 8 + cq + 4];
            HMMA16(o0[0], o0[1], o0[2], o0[3],
                   pa[2 * s], pb[2 * s], pa[2 * s + 1], pb[2 * s + 1], b0, b1);
            uint32_t b2 = sV[cur][(r + 8) * 68 + s * 8 + cq];
            uint32_t b3 = sV[cur][(r + 8) * 68 + s * 8 + cq + 4];
            HMMA16(o1[0], o1[1], o1[2], o1[3],
                   pa[2 * s], pb[2 * s], pa[2 * s + 1], pb[2 * s + 1], b2, b3);
        }

        if (c + 1 < NCHUNK) {
            int nxt = cur ^ 1;
            ((uint2*)sK[nxt])[t] = kreg;
            *(uint4*)&sV[nxt][pl * 68 + qw * 4] = vreg;
        }
        __syncthreads();
    }

    float ss_lo = __shfl_sync(0xffffffffu, o1[0], lane & ~3);
    float ss_hi = __shfl_sync(0xffffffffu, o1[2], lane & ~3);
    float inv_lo = 1.f / fmaxf(ss_lo, 1e-30f);
    float inv_hi = 1.f / fmaxf(ss_hi, 1e-30f);

    int n = nh >> 3, h = nh & 7;
    float* dst = g_o + ((size_t)n * HCH + h * 8 + cq * 2) * L + q0 + r;
    dst[0]     = o0[0] * inv_lo;
    dst[8]     = o0[2] * inv_hi;
    dst[L]     = o0[1] * inv_lo;
    dst[L + 8] = o0[3] * inv_hi;
}

// ============================================================
// Pos 3x3 conv as implicit GEMM over V, K-split 4x, atomicAdd merge.
// grid (72, 4, 4) = 1152 CTAs.
// ============================================================
__global__ void __launch_bounds__(256) pos_gemm_kernel(
    const float* __restrict__ pw, const float* __restrict__ pb)
{
    __shared__ float As[16][68];
    __shared__ float Bs[16][36];
    int n  = blockIdx.z;
    int ky = blockIdx.y;
    int l0 = blockIdx.x * 32;
    int t  = threadIdx.x;
    int tm = t >> 4, tn = t & 15;

    float acc[4][2];
#pragma unroll
    for (int i = 0; i < 4; i++) { acc[i][0] = 0.f; acc[i][1] = 0.f; }

    int kbase = ky * 144;
    for (int k0 = kbase; k0 < kbase + 144; k0 += 16) {
        {
            int m = t >> 2, kk = (t & 3) * 4;
            float4 a = *(const float4*)(pw + (size_t)m * 576 + k0 + kk);
            As[kk + 0][m] = a.x; As[kk + 1][m] = a.y;
            As[kk + 2][m] = a.z; As[kk + 3][m] = a.w;
        }
        {
#pragma unroll
            for (int u = 0; u < 2; u++) {
                int e = t * 2 + u;
                int kk = e >> 5, col = e & 31;
                int k = k0 + kk;
                int ic = k / 9;
                int tap = k - ic * 9;
                int dy = tap / 3 - 1, dx = tap - (tap / 3) * 3 - 1;
                int px = l0 + col;
                int y = px / 48, x = px - y * 48;
                int gy = y + dy, gx = x + dx;
                float v = 0.f;
                if ((unsigned)gy < 48u && (unsigned)gx < 48u) {
                    int c = (ic >> 3) * 24 + 16 + (ic & 7);
                    v = g_qkv[((size_t)n * 192 + c) * L + gy * 48 + gx];
                }
                Bs[kk][col] = v;
            }
        }
        __syncthreads();
#pragma unroll
        for (int kk = 0; kk < 16; kk++) {
            float4 a4 = *(const float4*)&As[kk][tm * 4];
            float2 b2 = *(const float2*)&Bs[kk][tn * 2];
            float ar[4] = {a4.x, a4.y, a4.z, a4.w};
#pragma unroll
            for (int i = 0; i < 4; i++) {
                acc[i][0] = fmaf(ar[i], b2.x, acc[i][0]);
                acc[i][1] = fmaf(ar[i], b2.y, acc[i][1]);
            }
        }
        __syncthreads();
    }

#pragma unroll
    for (int i = 0; i < 4; i++) {
        int m = tm * 4 + i;
        float bb = (ky == 0) ? pb[m] : 0.f;
        float* dst = g_o + ((size_t)n * HCH + m) * L + l0 + tn * 2;
        atomicAdd(dst,     acc[i][0] + bb);
        atomicAdd(dst + 1, acc[i][1] + bb);
    }
}

// ============================================================
extern "C" void kernel_launch(void* const* d_in, const int* in_sizes, int n_in,
                              void* d_out, int out_size)
{
    const float* x     = (const float*)d_in[0];
    const float* qkv_w = (const float*)d_in[1];
    const float* qkv_b = (const float*)d_in[2];
    const float* pos_w = (const float*)d_in[3];
    const float* pos_b = (const float*)d_in[4];
    const float* res_w = (const float*)d_in[5];
    const float* res_b = (const float*)d_in[6];
    float* out = (float*)d_out;

    float* qkv_ptr = nullptr;
    float* o_ptr   = nullptr;
    cudaGetSymbolAddress((void**)&qkv_ptr, g_qkv);
    cudaGetSymbolAddress((void**)&o_ptr, g_o);
    uint4 *qwf, *rwf, *xf, *of;
    cudaGetSymbolAddress((void**)&qwf, g_qwf);
    cudaGetSymbolAddress((void**)&rwf, g_rwf);
    cudaGetSymbolAddress((void**)&xf, g_xf);
    cudaGetSymbolAddress((void**)&of, g_of);

    // K0: zero g_qkv (atomicAdd target for K-split qkv GEMM)
    cudaMemsetAsync(qkv_ptr, 0, (size_t)NBATCH * 192 * L * sizeof(float));

    // K1a: build A-frags for qkv_w [192x512] and res_w [512x64]
    afrag_split_kernel<<<48, 256>>>(qkv_w, qwf, 512, 32, 12 * 32 * 32);
    afrag_split_kernel<<<16, 256>>>(res_w, rwf, 64, 4, 32 * 4 * 32);
    // K1b: build B-frags for x
    {
        int total = NBATCH * NCB * 32 * 32;
        bfrag_split_kernel<<<(total + 255) / 256, 256>>>(x, xf, 512, 32, total);
    }
    // K1c: qkv GEMM (split-f16 HMMA, K-split 2x, atomicAdd) -> g_qkv
    hgemm_split_kernel<32, 2, 1><<<dim3(36, 6, NBATCH), 256>>>(
        qwf, xf, qkv_b, qkv_ptr, 192);

    // K2: attention fragment images
    {
        int total = NT_Q + NT_K + NT_V;
        convert_kernel<<<(total + 255) / 256, 256>>>();
    }

    // K3: attention (HMMA tensor cores)
    attn_hmma_kernel<<<NNH * NQT, 256>>>();

    // K4: pos conv (K-split 4x, atomicAdd into g_o)
    pos_gemm_kernel<<<dim3(72, 4, NBATCH), 256>>>(pos_w, pos_b);

    // K5a: build B-frags for attention+pos output
    {
        int total = NBATCH * NCB * 4 * 32;
        bfrag_split_kernel<<<(total + 255) / 256, 256>>>(o_ptr, of, 64, 4, total);
    }
    // K5b: res GEMM (split-f16 HMMA) -> out
    hgemm_split_kernel<4, 1, 0><<<dim3(36, 8, NBATCH), 256>>>(
        rwf, of, res_b, out, 512);
}

// round 15
// speedup vs baseline: 1.6792x; 1.0601x over previous
#include <cuda_runtime.h>
#include <cuda_fp16.h>
#include <cstdint>

#define L 2304
#define NBATCH 4
#define CIN 512
#define HCH 64
#define NH 8
#define NNH (NBATCH * NH)        // 32
#define NQT 18                   // q tiles of 128
#define NCHUNK 18                // key chunks of 128
#define NCB 288                  // column blocks of 8 over L

// scratch (no cudaMalloc allowed)
__device__ float g_qkv[NBATCH * 192 * L];        // [n][192][L] fp32
__device__ float g_o[NBATCH * HCH * L];          // [n][64][L]
__device__ __half g_qh[NNH * L * 8];             // [nh][q][8]  (scaled)
__device__ __half g_kh[NNH * L * 8];             // [nh][k][8]
__device__ __half g_vh[NNH * 16 * L];            // [nh][dim16][k], plane8=ones
// split-f16 fragment images (hi/lo interleaved)
__device__ uint4 g_qwf[12 * 32 * 32 * 2];        // qkv_w A-frags {hi,lo}
__device__ uint4 g_rwf[32 * 4 * 32 * 2];         // res_w A-frags
__device__ uint4 g_pwf[4 * 36 * 32 * 2];         // pos_w A-frags (64x576)
__device__ uint4 g_xf[NBATCH * NCB * 32 * 32];   // x B-frags {bh0,bh1,bl0,bl1}
__device__ uint4 g_of[NBATCH * NCB * 4 * 32];    // attn-out B-frags
__device__ uint4 g_pf[NBATCH * NCB * 36 * 32];   // pos im2col B-frags

#define HMMA16(c0, c1, c2, c3, a0, a1, a2, a3, b0, b1) \
    asm volatile("mma.sync.aligned.m16n8k16.row.col.f32.f16.f16.f32 " \
        "{%0,%1,%2,%3}, {%4,%5,%6,%7}, {%8,%9}, {%0,%1,%2,%3};" \
        : "+f"(c0), "+f"(c1), "+f"(c2), "+f"(c3) \
        : "r"(a0), "r"(a1), "r"(a2), "r"(a3), "r"(b0), "r"(b1))

#define HMMA8(c0, c1, c2, c3, a0, a1, b0) \
    asm volatile("mma.sync.aligned.m16n8k8.row.col.f32.f16.f16.f32 " \
        "{%0,%1,%2,%3}, {%4,%5}, {%6}, {%0,%1,%2,%3};" \
        : "+f"(c0), "+f"(c1), "+f"(c2), "+f"(c3) \
        : "r"(a0), "r"(a1), "r"(b0))

__device__ __forceinline__ uint32_t split_pack(float a, float b, uint32_t& lo) {
    __half ha = __float2half_rn(a), hb = __float2half_rn(b);
    __half la = __float2half_rn(a - __half2float(ha));
    __half lb = __float2half_rn(b - __half2float(hb));
    lo = ((uint32_t)__half_as_ushort(lb) << 16) | __half_as_ushort(la);
    return ((uint32_t)__half_as_ushort(hb) << 16) | __half_as_ushort(ha);
}

// ============================================================
// A-fragment builder: src [M][K] fp32 -> {hi,lo} uint4 pairs.
// ============================================================
__global__ void __launch_bounds__(256) afrag_split_kernel(
    const float* __restrict__ src, uint4* __restrict__ dst,
    int K, int NKB, int total)
{
    int id = blockIdx.x * 256 + threadIdx.x;
    if (id >= total) return;
    int lane = id & 31;
    int kblk = (id >> 5) % NKB;
    int mb   = id / (32 * NKB);
    int row = mb * 16 + (lane >> 2);
    int w   = kblk * 8 + (lane & 3);
    const float* s0 = src + (size_t)row * K;
    const float* s1 = s0 + 8 * K;
    uint4 hi, lo;
    hi.x = split_pack(s0[2 * w],     s0[2 * w + 1], lo.x);
    hi.y = split_pack(s1[2 * w],     s1[2 * w + 1], lo.y);
    hi.z = split_pack(s0[2 * w + 8], s0[2 * w + 9], lo.z);
    hi.w = split_pack(s1[2 * w + 8], s1[2 * w + 9], lo.w);
    dst[id * 2]     = hi;
    dst[id * 2 + 1] = lo;
}

// ============================================================
// B-fragment builder: src [nb][Kch][L] -> uint4 {bh0,bh1,bl0,bl1}.
// ============================================================
__global__ void __launch_bounds__(256) bfrag_split_kernel(
    const float* __restrict__ src, uint4* __restrict__ dst,
    int Kch, int NKB, int total)
{
    int id = blockIdx.x * 256 + threadIdx.x;
    if (id >= total) return;
    int lane = id & 31;
    int kblk = (id >> 5) % NKB;
    int cb   = (id / (32 * NKB)) % NCB;
    int nb   = id / (32 * NKB * NCB);
    int col = cb * 8 + (lane >> 2);
    int w   = kblk * 8 + (lane & 3);
    const float* s = src + (size_t)nb * Kch * L + col;
    uint4 o;
    o.x = split_pack(s[(size_t)(2 * w) * L],     s[(size_t)(2 * w + 1) * L], o.z);
    o.y = split_pack(s[(size_t)(2 * w + 8) * L], s[(size_t)(2 * w + 9) * L], o.w);
    dst[id] = o;
}

// ============================================================
// Pos-conv im2col B-fragment builder: channel k = ic*9+tap,
// value = V[n][ic][shift(px, tap)] (0 outside), V from g_qkv.
// Same [nb][cb][kblk][lane] uint4 layout as bfrag.
// ============================================================
__device__ __forceinline__ float pos_im2col(const float* qn, int k, int px) {
    int ic = k / 9;
    int tap = k - ic * 9;
    int dy = tap / 3 - 1, dx = tap - (tap / 3) * 3 - 1;
    int y = px / 48, x = px - y * 48;
    int gy = y + dy, gx = x + dx;
    float v = 0.f;
    if ((unsigned)gy < 48u && (unsigned)gx < 48u) {
        int c = (ic >> 3) * 24 + 16 + (ic & 7);   // V channel in qkv
        v = qn[(size_t)c * L + gy * 48 + gx];
    }
    return v;
}

__global__ void __launch_bounds__(256) pfrag_split_kernel(int total)
{
    int id = blockIdx.x * 256 + threadIdx.x;
    if (id >= total) return;
    int lane = id & 31;
    int kblk = (id >> 5) % 36;
    int cb   = (id / (32 * 36)) % NCB;
    int nb   = id / (32 * 36 * NCB);
    int px = cb * 8 + (lane >> 2);
    int w  = kblk * 8 + (lane & 3);
    const float* qn = g_qkv + (size_t)nb * 192 * L;
    uint4 o;
    o.x = split_pack(pos_im2col(qn, 2 * w, px),     pos_im2col(qn, 2 * w + 1, px), o.z);
    o.y = split_pack(pos_im2col(qn, 2 * w + 8, px), pos_im2col(qn, 2 * w + 9, px), o.w);
    g_pf[id] = o;
}

// ============================================================
// Split-f16 HMMA GEMM, templated NKB/ksplit, 4m x 2n warp layout.
// C[nb][m][l] = sum_k A[m][k]*B[nb][k][l] (+bias).
// ADDMODE=1: atomicAdd into C, bias applied by ky==0.
// grid (36, MBT*KSPLIT, NBATCH), 256 thr = 8 warps (4 m16 x 2 cb4).
// ============================================================
template <int NKB, int KSPLIT, int ADDMODE>
__global__ void __launch_bounds__(256, 3) hgemm_split_kernel(
    const uint4* __restrict__ Af, const uint4* __restrict__ Bf,
    const float* __restrict__ bias, float* __restrict__ C,
    int M)
{
    constexpr int kbN = NKB / KSPLIT;
    int t = threadIdx.x, wid = t >> 5, lane = t & 31;
    int mw = wid >> 1, nw = wid & 1;
    int mbt = blockIdx.y / KSPLIT;
    int ky  = blockIdx.y % KSPLIT;
    int mb  = mbt * 4 + mw;
    int cb0 = blockIdx.x * 8 + nw * 4;
    int nb  = blockIdx.z;
    int r = lane >> 2, cq = lane & 3;
    int kb0 = ky * kbN;

    const uint4* pa = Af + ((size_t)mb * NKB + kb0) * 64 + lane * 2;
    const uint4* pb = Bf + (((size_t)nb * NCB + cb0) * NKB + kb0) * 32 + lane;

    float acc[4][4];
#pragma unroll
    for (int j = 0; j < 4; j++)
#pragma unroll
        for (int i = 0; i < 4; i++) acc[j][i] = 0.f;

    uint4 nB[4];
#pragma unroll
    for (int j = 0; j < 4; j++) nB[j] = pb[j * (NKB * 32)];

#pragma unroll 4
    for (int kb = 0; kb < kbN; kb++) {
        uint4 cB[4];
#pragma unroll
        for (int j = 0; j < 4; j++) cB[j] = nB[j];
        uint4 ah = pa[0];
        uint4 al = pa[1];
        if (kb + 1 < kbN) {
            pb += 32;
            pa += 64;
#pragma unroll
            for (int j = 0; j < 4; j++) nB[j] = pb[j * (NKB * 32)];
        }
#pragma unroll
        for (int j = 0; j < 4; j++) {
            HMMA16(acc[j][0], acc[j][1], acc[j][2], acc[j][3],
                   ah.x, ah.y, ah.z, ah.w, cB[j].x, cB[j].y);
            HMMA16(acc[j][0], acc[j][1], acc[j][2], acc[j][3],
                   ah.x, ah.y, ah.z, ah.w, cB[j].z, cB[j].w);
            HMMA16(acc[j][0], acc[j][1], acc[j][2], acc[j][3],
                   al.x, al.y, al.z, al.w, cB[j].x, cB[j].y);
        }
    }

    int row0 = mb * 16 + r;
    float b0 = 0.f, b1 = 0.f;
    if (!ADDMODE || ky == 0) { b0 = bias[row0]; b1 = bias[row0 + 8]; }
    float* base0 = C + ((size_t)nb * M + row0) * L;
    float* base1 = base0 + 8 * L;
#pragma unroll
    for (int j = 0; j < 4; j++) {
        int col = (cb0 + j) * 8 + cq * 2;
        float v00 = acc[j][0] + b0;
        float v01 = acc[j][1] + b0;
        float v10 = acc[j][2] + b1;
        float v11 = acc[j][3] + b1;
        if (ADDMODE) {
            atomicAdd(base0 + col,     v00);
            atomicAdd(base0 + col + 1, v01);
            atomicAdd(base1 + col,     v10);
            atomicAdd(base1 + col + 1, v11);
        } else {
            *(float2*)(base0 + col) = make_float2(v00, v01);
            *(float2*)(base1 + col) = make_float2(v10, v11);
        }
    }
}

// ============================================================
// Convert fp32 qkv -> fp16 fragment-friendly images (attention).
// ============================================================
#define NT_Q (NNH * L)
#define NT_K (NNH * L)
#define NT_V (NNH * 16 * (L / 8))

__global__ void __launch_bounds__(256) convert_kernel()
{
    const float QS = 0.35355339059327373f * 1.4426950408889634f;
    int id = blockIdx.x * 256 + threadIdx.x;

    if (id < NT_Q) {
        int nh = id / L, q = id - nh * L;
        int n = nh >> 3, h = nh & 7;
        const float* src = g_qkv + ((size_t)n * 192 + h * 24) * L + q;
        uint32_t w[4];
#pragma unroll
        for (int j = 0; j < 4; j++) {
            __half2 h2 = __floats2half2_rn(src[(size_t)(2 * j) * L] * QS,
                                           src[(size_t)(2 * j + 1) * L] * QS);
            w[j] = *(uint32_t*)&h2;
        }
        ((uint4*)g_qh)[id] = make_uint4(w[0], w[1], w[2], w[3]);
        return;
    }
    id -= NT_Q;
    if (id < NT_K) {
        int nh = id / L, k = id - nh * L;
        int n = nh >> 3, h = nh & 7;
        const float* src = g_qkv + ((size_t)n * 192 + h * 24 + 8) * L + k;
        uint32_t w[4];
#pragma unroll
        for (int j = 0; j < 4; j++) {
            __half2 h2 = __floats2half2_rn(src[(size_t)(2 * j) * L],
                                           src[(size_t)(2 * j + 1) * L]);
            w[j] = *(uint32_t*)&h2;
        }
        ((uint4*)g_kh)[id] = make_uint4(w[0], w[1], w[2], w[3]);
        return;
    }
    id -= NT_K;
    if (id < NT_V) {
        int nh = id / (16 * (L / 8));
        int rem = id - nh * 16 * (L / 8);
        int dim = rem / (L / 8);
        int blk = rem - dim * (L / 8);
        uint4 out;
        if (dim < 8) {
            int n = nh >> 3, h = nh & 7;
            const float* src = g_qkv + ((size_t)n * 192 + h * 24 + 16 + dim) * L + blk * 8;
            float4 f0 = *(const float4*)src;
            float4 f1 = *(const float4*)(src + 4);
            __half2 a = __floats2half2_rn(f0.x, f0.y);
            __half2 b = __floats2half2_rn(f0.z, f0.w);
            __half2 c = __floats2half2_rn(f1.x, f1.y);
            __half2 d = __floats2half2_rn(f1.z, f1.w);
            out = make_uint4(*(uint32_t*)&a, *(uint32_t*)&b, *(uint32_t*)&c, *(uint32_t*)&d);
        } else if (dim == 8) {
            out = make_uint4(0x3C003C00u, 0x3C003C00u, 0x3C003C00u, 0x3C003C00u);
        } else {
            out = make_uint4(0, 0, 0, 0);
        }
        ((uint4*)g_vh)[(size_t)(nh * 16 + dim) * (L / 8) + blk] = out;
    }
}

// ============================================================
// Attention via HMMA (f16 in, f32 accum).
// ============================================================
__global__ void __launch_bounds__(256) attn_hmma_kernel()
{
    __shared__ uint32_t sK[2][512];
    __shared__ uint32_t sV[2][16 * 68];
    int t = threadIdx.x, wid = t >> 5, lane = t & 31;
    int bid = blockIdx.x;
    int qt = bid % NQT;
    int nh = bid / NQT;
    int r = lane >> 2, cq = lane & 3;

    const uint32_t* kg = (const uint32_t*)g_kh + (size_t)nh * L * 4;
    const uint32_t* vg = (const uint32_t*)g_vh + (size_t)nh * 16 * (L / 2);

    int q0 = qt * 128 + wid * 16;
    const uint32_t* qgp = (const uint32_t*)g_qh + (size_t)(nh * L + q0) * 4;
    uint32_t qa0 = qgp[r * 4 + cq];
    uint32_t qa1 = qgp[(r + 8) * 4 + cq];
    const uint32_t C15 = 0x4B804B80u;

    int pl = t >> 4, qw = t & 15;

    uint2 kreg = ((const uint2*)kg)[t];
    uint4 vreg = *(const uint4*)(vg + (size_t)pl * (L / 2) + qw * 4);
    ((uint2*)sK[0])[t] = kreg;
    *(uint4*)&sV[0][pl * 68 + qw * 4] = vreg;
    __syncthreads();

    float o0[4] = {0.f, 0.f, 0.f, 0.f};
    float o1[4] = {0.f, 0.f, 0.f, 0.f};

    for (int c = 0; c < NCHUNK; c++) {
        int cur = c & 1;
        if (c + 1 < NCHUNK) {
            kreg = ((const uint2*)(kg + (size_t)(c + 1) * 512))[t];
            vreg = *(const uint4*)(vg + (size_t)pl * (L / 2) + (c + 1) * 64 + qw * 4);
        }

        uint32_t pa[16], pb[16];
#pragma unroll
        for (int j = 0; j < 16; j++) {
            uint32_t kb = sK[cur][j * 32 + r * 4 + cq];
            float s0 = -9.f, s1 = -9.f, s2 = -9.f, s3 = -9.f;
            HMMA8(s0, s1, s2, s3, qa0, qa1, kb);
            uint32_t x, y;
            asm("cvt.rn.f16x2.f32 %0, %1, %2;" : "=r"(x) : "f"(s1), "f"(s0));
            asm("min.f16x2 %0, %0, %1;" : "+r"(x) : "r"(C15));
            asm("ex2.approx.f16x2 %0, %1;" : "=r"(x) : "r"(x));
            asm("cvt.rn.f16x2.f32 %0, %1, %2;" : "=r"(y) : "f"(s3), "f"(s2));
            asm("min.f16x2 %0, %0, %1;" : "+r"(y) : "r"(C15));
            asm("ex2.approx.f16x2 %0, %1;" : "=r"(y) : "r"(y));
            pa[j] = x;
            pb[j] = y;
        }

#pragma unroll
        for (int s = 0; s < 8; s++) {
            uint32_t b0 = sV[cur][r * 68 + s * 8 + cq];
            uint32_t b1 = sV[cur][r * 68 + s * 8 + cq + 4];
            HMMA16(o0[0], o0[1], o0[2], o0[3],
                   pa[2 * s], pb[2 * s], pa[2 * s + 1], pb[2 * s + 1], b0, b1);
            uint32_t b2 = sV[cur][(r + 8) * 68 + s * 8 + cq];
            uint32_t b3 = sV[cur][(r + 8) * 68 + s * 8 + cq + 4];
            HMMA16(o1[0], o1[1], o1[2], o1[3],
                   pa[2 * s], pb[2 * s], pa[2 * s + 1], pb[2 * s + 1], b2, b3);
        }

        if (c + 1 < NCHUNK) {
            int nxt = cur ^ 1;
            ((uint2*)sK[nxt])[t] = kreg;
            *(uint4*)&sV[nxt][pl * 68 + qw * 4] = vreg;
        }
        __syncthreads();
    }

    float ss_lo = __shfl_sync(0xffffffffu, o1[0], lane & ~3);
    float ss_hi = __shfl_sync(0xffffffffu, o1[2], lane & ~3);
    float inv_lo = 1.f / fmaxf(ss_lo, 1e-30f);
    float inv_hi = 1.f / fmaxf(ss_hi, 1e-30f);

    int n = nh >> 3, h = nh & 7;
    float* dst = g_o + ((size_t)n * HCH + h * 8 + cq * 2) * L + q0 + r;
    dst[0]     = o0[0] * inv_lo;
    dst[8]     = o0[2] * inv_hi;
    dst[L]     = o0[1] * inv_lo;
    dst[L + 8] = o0[3] * inv_hi;
}

// ============================================================
extern "C" void kernel_launch(void* const* d_in, const int* in_sizes, int n_in,
                              void* d_out, int out_size)
{
    const float* x     = (const float*)d_in[0];
    const float* qkv_w = (const float*)d_in[1];
    const float* qkv_b = (const float*)d_in[2];
    const float* pos_w = (const float*)d_in[3];
    const float* pos_b = (const float*)d_in[4];
    const float* res_w = (const float*)d_in[5];
    const float* res_b = (const float*)d_in[6];
    float* out = (float*)d_out;

    float* qkv_ptr = nullptr;
    float* o_ptr   = nullptr;
    cudaGetSymbolAddress((void**)&qkv_ptr, g_qkv);
    cudaGetSymbolAddress((void**)&o_ptr, g_o);
    uint4 *qwf, *rwf, *pwf, *xf, *of, *pf;
    cudaGetSymbolAddress((void**)&qwf, g_qwf);
    cudaGetSymbolAddress((void**)&rwf, g_rwf);
    cudaGetSymbolAddress((void**)&pwf, g_pwf);
    cudaGetSymbolAddress((void**)&xf, g_xf);
    cudaGetSymbolAddress((void**)&of, g_of);
    cudaGetSymbolAddress((void**)&pf, g_pf);

    // K0: zero g_qkv (atomicAdd target for K-split qkv GEMM)
    cudaMemsetAsync(qkv_ptr, 0, (size_t)NBATCH * 192 * L * sizeof(float));

    // K1a: build A-frags (qkv_w 192x512, res_w 512x64, pos_w 64x576)
    afrag_split_kernel<<<48, 256>>>(qkv_w, qwf, 512, 32, 12 * 32 * 32);
    afrag_split_kernel<<<16, 256>>>(res_w, rwf, 64, 4, 32 * 4 * 32);
    afrag_split_kernel<<<18, 256>>>(pos_w, pwf, 576, 36, 4 * 36 * 32);
    // K1b: build B-frags for x
    {
        int total = NBATCH * NCB * 32 * 32;
        bfrag_split_kernel<<<(total + 255) / 256, 256>>>(x, xf, 512, 32, total);
    }
    // K1c: qkv GEMM (split-f16 HMMA, K-split 2x, atomicAdd) -> g_qkv
    hgemm_split_kernel<32, 2, 1><<<dim3(36, 6, NBATCH), 256>>>(
        qwf, xf, qkv_b, qkv_ptr, 192);

    // K2: attention fragment images
    {
        int total = NT_Q + NT_K + NT_V;
        convert_kernel<<<(total + 255) / 256, 256>>>();
    }

    // K3: attention (HMMA tensor cores) -> g_o
    attn_hmma_kernel<<<NNH * NQT, 256>>>();

    // K4a: build pos im2col B-frags from V
    {
        int total = NBATCH * NCB * 36 * 32;
        pfrag_split_kernel<<<(total + 255) / 256, 256>>>(total);
    }
    // K4b: pos conv GEMM (split-f16 HMMA, K-split 4x, atomicAdd into g_o)
    hgemm_split_kernel<36, 4, 1><<<dim3(36, 4, NBATCH), 256>>>(
        pwf, pf, pos_b, o_ptr, 64);

    // K5a: build B-frags for attention+pos output
    {
        int total = NBATCH * NCB * 4 * 32;
        bfrag_split_kernel<<<(total + 255) / 256, 256>>>(o_ptr, of, 64, 4, total);
    }
    // K5b: res GEMM (split-f16 HMMA) -> out
    hgemm_split_kernel<4, 1, 0><<<dim3(36, 8, NBATCH), 256>>>(
        rwf, of, res_b, out, 512);
}

// round 16
// speedup vs baseline: 1.8047x; 1.0747x over previous
#include <cuda_runtime.h>
#include <cuda_fp16.h>
#include <cstdint>

#define L 2304
#define NBATCH 4
#define CIN 512
#define HCH 64
#define NH 8
#define NNH (NBATCH * NH)        // 32
#define NQT 18                   // q tiles of 128
#define NCHUNK 18                // key chunks of 128
#define NCB 288                  // column blocks of 8 over L

// scratch (no cudaMalloc allowed)
__device__ float g_qkv[NBATCH * 192 * L];        // [n][192][L] fp32
__device__ float g_o[NBATCH * HCH * L];          // [n][64][L]
__device__ __half g_qh[NNH * L * 8];             // [nh][q][8]  (scaled)
__device__ __half g_kh[NNH * L * 8];             // [nh][k][8]
__device__ __half g_vh[NNH * 16 * L];            // [nh][dim16][k], plane8=ones
// fragment images
__device__ uint4 g_qwf[12 * 32 * 32 * 2];        // qkv_w A-frags {hi,lo}
__device__ uint4 g_rwf[32 * 4 * 32 * 2];         // res_w A-frags
__device__ uint4 g_pwf[4 * 36 * 32 * 2];         // pos_w A-frags (64x576)
__device__ uint2 g_xf2[NBATCH * NCB * 32 * 32];  // x B-frags hi-only {bh0,bh1}
__device__ uint4 g_of[NBATCH * NCB * 4 * 32];    // attn-out B-frags (full split)
__device__ uint2 g_pf2[NBATCH * NCB * 36 * 32];  // pos im2col B-frags hi-only

#define HMMA16(c0, c1, c2, c3, a0, a1, a2, a3, b0, b1) \
    asm volatile("mma.sync.aligned.m16n8k16.row.col.f32.f16.f16.f32 " \
        "{%0,%1,%2,%3}, {%4,%5,%6,%7}, {%8,%9}, {%0,%1,%2,%3};" \
        : "+f"(c0), "+f"(c1), "+f"(c2), "+f"(c3) \
        : "r"(a0), "r"(a1), "r"(a2), "r"(a3), "r"(b0), "r"(b1))

#define HMMA8(c0, c1, c2, c3, a0, a1, b0) \
    asm volatile("mma.sync.aligned.m16n8k8.row.col.f32.f16.f16.f32 " \
        "{%0,%1,%2,%3}, {%4,%5}, {%6}, {%0,%1,%2,%3};" \
        : "+f"(c0), "+f"(c1), "+f"(c2), "+f"(c3) \
        : "r"(a0), "r"(a1), "r"(b0))

__device__ __forceinline__ uint32_t split_pack(float a, float b, uint32_t& lo) {
    __half ha = __float2half_rn(a), hb = __float2half_rn(b);
    __half la = __float2half_rn(a - __half2float(ha));
    __half lb = __float2half_rn(b - __half2float(hb));
    lo = ((uint32_t)__half_as_ushort(lb) << 16) | __half_as_ushort(la);
    return ((uint32_t)__half_as_ushort(hb) << 16) | __half_as_ushort(ha);
}

__device__ __forceinline__ uint32_t pack_h2(float a, float b) {
    __half2 h2 = __floats2half2_rn(a, b);
    return *(uint32_t*)&h2;
}

// ============================================================
// A-fragment builder: src [M][K] fp32 -> {hi,lo} uint4 pairs.
// ============================================================
__global__ void __launch_bounds__(256) afrag_split_kernel(
    const float* __restrict__ src, uint4* __restrict__ dst,
    int K, int NKB, int total)
{
    int id = blockIdx.x * 256 + threadIdx.x;
    if (id >= total) return;
    int lane = id & 31;
    int kblk = (id >> 5) % NKB;
    int mb   = id / (32 * NKB);
    int row = mb * 16 + (lane >> 2);
    int w   = kblk * 8 + (lane & 3);
    const float* s0 = src + (size_t)row * K;
    const float* s1 = s0 + 8 * K;
    uint4 hi, lo;
    hi.x = split_pack(s0[2 * w],     s0[2 * w + 1], lo.x);
    hi.y = split_pack(s1[2 * w],     s1[2 * w + 1], lo.y);
    hi.z = split_pack(s0[2 * w + 8], s0[2 * w + 9], lo.z);
    hi.w = split_pack(s1[2 * w + 8], s1[2 * w + 9], lo.w);
    dst[id * 2]     = hi;
    dst[id * 2 + 1] = lo;
}

// ============================================================
// B-fragment builder, full split: src [nb][Kch][L] -> uint4.
// ============================================================
__global__ void __launch_bounds__(256) bfrag_split_kernel(
    const float* __restrict__ src, uint4* __restrict__ dst,
    int Kch, int NKB, int total)
{
    int id = blockIdx.x * 256 + threadIdx.x;
    if (id >= total) return;
    int lane = id & 31;
    int kblk = (id >> 5) % NKB;
    int cb   = (id / (32 * NKB)) % NCB;
    int nb   = id / (32 * NKB * NCB);
    int col = cb * 8 + (lane >> 2);
    int w   = kblk * 8 + (lane & 3);
    const float* s = src + (size_t)nb * Kch * L + col;
    uint4 o;
    o.x = split_pack(s[(size_t)(2 * w) * L],     s[(size_t)(2 * w + 1) * L], o.z);
    o.y = split_pack(s[(size_t)(2 * w + 8) * L], s[(size_t)(2 * w + 9) * L], o.w);
    dst[id] = o;
}

// ============================================================
// B-fragment builder, hi-only f16: src [nb][Kch][L] -> uint2.
// ============================================================
__global__ void __launch_bounds__(256) bfrag_hi_kernel(
    const float* __restrict__ src, uint2* __restrict__ dst,
    int Kch, int NKB, int total)
{
    int id = blockIdx.x * 256 + threadIdx.x;
    if (id >= total) return;
    int lane = id & 31;
    int kblk = (id >> 5) % NKB;
    int cb   = (id / (32 * NKB)) % NCB;
    int nb   = id / (32 * NKB * NCB);
    int col = cb * 8 + (lane >> 2);
    int w   = kblk * 8 + (lane & 3);
    const float* s = src + (size_t)nb * Kch * L + col;
    uint2 o;
    o.x = pack_h2(s[(size_t)(2 * w) * L],     s[(size_t)(2 * w + 1) * L]);
    o.y = pack_h2(s[(size_t)(2 * w + 8) * L], s[(size_t)(2 * w + 9) * L]);
    dst[id] = o;
}

// ============================================================
// Pos-conv im2col B-frag builder (hi-only f16).
// channel k = ic*9+tap, value = V[n][ic][shift(px, tap)].
// ============================================================
__device__ __forceinline__ float pos_im2col(const float* qn, int k, int px) {
    int ic = k / 9;
    int tap = k - ic * 9;
    int dy = tap / 3 - 1, dx = tap - (tap / 3) * 3 - 1;
    int y = px / 48, x = px - y * 48;
    int gy = y + dy, gx = x + dx;
    float v = 0.f;
    if ((unsigned)gy < 48u && (unsigned)gx < 48u) {
        int c = (ic >> 3) * 24 + 16 + (ic & 7);   // V channel in qkv
        v = qn[(size_t)c * L + gy * 48 + gx];
    }
    return v;
}

__global__ void __launch_bounds__(256) pfrag_hi_kernel(int total)
{
    int id = blockIdx.x * 256 + threadIdx.x;
    if (id >= total) return;
    int lane = id & 31;
    int kblk = (id >> 5) % 36;
    int cb   = (id / (32 * 36)) % NCB;
    int nb   = id / (32 * 36 * NCB);
    int px = cb * 8 + (lane >> 2);
    int w  = kblk * 8 + (lane & 3);
    const float* qn = g_qkv + (size_t)nb * 192 * L;
    uint2 o;
    o.x = pack_h2(pos_im2col(qn, 2 * w, px),     pos_im2col(qn, 2 * w + 1, px));
    o.y = pack_h2(pos_im2col(qn, 2 * w + 8, px), pos_im2col(qn, 2 * w + 9, px));
    g_pf2[id] = o;
}

// ============================================================
// Split-A x full-split-B HMMA GEMM (3 HMMA/j) — used for res.
// ============================================================
template <int NKB, int KSPLIT, int ADDMODE>
__global__ void __launch_bounds__(256, 3) hgemm_split_kernel(
    const uint4* __restrict__ Af, const uint4* __restrict__ Bf,
    const float* __restrict__ bias, float* __restrict__ C,
    int M)
{
    constexpr int kbN = NKB / KSPLIT;
    int t = threadIdx.x, wid = t >> 5, lane = t & 31;
    int mw = wid >> 1, nw = wid & 1;
    int mbt = blockIdx.y / KSPLIT;
    int ky  = blockIdx.y % KSPLIT;
    int mb  = mbt * 4 + mw;
    int cb0 = blockIdx.x * 8 + nw * 4;
    int nb  = blockIdx.z;
    int r = lane >> 2, cq = lane & 3;
    int kb0 = ky * kbN;

    const uint4* pa = Af + ((size_t)mb * NKB + kb0) * 64 + lane * 2;
    const uint4* pb = Bf + (((size_t)nb * NCB + cb0) * NKB + kb0) * 32 + lane;

    float acc[4][4];
#pragma unroll
    for (int j = 0; j < 4; j++)
#pragma unroll
        for (int i = 0; i < 4; i++) acc[j][i] = 0.f;

    uint4 nB[4];
#pragma unroll
    for (int j = 0; j < 4; j++) nB[j] = pb[j * (NKB * 32)];

#pragma unroll 4
    for (int kb = 0; kb < kbN; kb++) {
        uint4 cB[4];
#pragma unroll
        for (int j = 0; j < 4; j++) cB[j] = nB[j];
        uint4 ah = pa[0];
        uint4 al = pa[1];
        if (kb + 1 < kbN) {
            pb += 32;
            pa += 64;
#pragma unroll
            for (int j = 0; j < 4; j++) nB[j] = pb[j * (NKB * 32)];
        }
#pragma unroll
        for (int j = 0; j < 4; j++) {
            HMMA16(acc[j][0], acc[j][1], acc[j][2], acc[j][3],
                   ah.x, ah.y, ah.z, ah.w, cB[j].x, cB[j].y);
            HMMA16(acc[j][0], acc[j][1], acc[j][2], acc[j][3],
                   ah.x, ah.y, ah.z, ah.w, cB[j].z, cB[j].w);
            HMMA16(acc[j][0], acc[j][1], acc[j][2], acc[j][3],
                   al.x, al.y, al.z, al.w, cB[j].x, cB[j].y);
        }
    }

    int row0 = mb * 16 + r;
    float b0 = 0.f, b1 = 0.f;
    if (!ADDMODE || ky == 0) { b0 = bias[row0]; b1 = bias[row0 + 8]; }
    float* base0 = C + ((size_t)nb * M + row0) * L;
    float* base1 = base0 + 8 * L;
#pragma unroll
    for (int j = 0; j < 4; j++) {
        int col = (cb0 + j) * 8 + cq * 2;
        float v00 = acc[j][0] + b0;
        float v01 = acc[j][1] + b0;
        float v10 = acc[j][2] + b1;
        float v11 = acc[j][3] + b1;
        if (ADDMODE) {
            atomicAdd(base0 + col,     v00);
            atomicAdd(base0 + col + 1, v01);
            atomicAdd(base1 + col,     v10);
            atomicAdd(base1 + col + 1, v11);
        } else {
            *(float2*)(base0 + col) = make_float2(v00, v01);
            *(float2*)(base1 + col) = make_float2(v10, v11);
        }
    }
}

// ============================================================
// Split-A x plain-f16-B HMMA GEMM (2 HMMA/j) — qkv + pos conv.
// ============================================================
template <int NKB, int KSPLIT, int ADDMODE>
__global__ void __launch_bounds__(256, 3) hgemm_bhi_kernel(
    const uint4* __restrict__ Af, const uint2* __restrict__ Bf,
    const float* __restrict__ bias, float* __restrict__ C,
    int M)
{
    constexpr int kbN = NKB / KSPLIT;
    int t = threadIdx.x, wid = t >> 5, lane = t & 31;
    int mw = wid >> 1, nw = wid & 1;
    int mbt = blockIdx.y / KSPLIT;
    int ky  = blockIdx.y % KSPLIT;
    int mb  = mbt * 4 + mw;
    int cb0 = blockIdx.x * 8 + nw * 4;
    int nb  = blockIdx.z;
    int r = lane >> 2, cq = lane & 3;
    int kb0 = ky * kbN;

    const uint4* pa = Af + ((size_t)mb * NKB + kb0) * 64 + lane * 2;
    const uint2* pb = Bf + (((size_t)nb * NCB + cb0) * NKB + kb0) * 32 + lane;

    float acc[4][4];
#pragma unroll
    for (int j = 0; j < 4; j++)
#pragma unroll
        for (int i = 0; i < 4; i++) acc[j][i] = 0.f;

    uint2 nB[4];
#pragma unroll
    for (int j = 0; j < 4; j++) nB[j] = pb[j * (NKB * 32)];

#pragma unroll 4
    for (int kb = 0; kb < kbN; kb++) {
        uint2 cB[4];
#pragma unroll
        for (int j = 0; j < 4; j++) cB[j] = nB[j];
        uint4 ah = pa[0];
        uint4 al = pa[1];
        if (kb + 1 < kbN) {
            pb += 32;
            pa += 64;
#pragma unroll
            for (int j = 0; j < 4; j++) nB[j] = pb[j * (NKB * 32)];
        }
#pragma unroll
        for (int j = 0; j < 4; j++) {
            HMMA16(acc[j][0], acc[j][1], acc[j][2], acc[j][3],
                   ah.x, ah.y, ah.z, ah.w, cB[j].x, cB[j].y);
            HMMA16(acc[j][0], acc[j][1], acc[j][2], acc[j][3],
                   al.x, al.y, al.z, al.w, cB[j].x, cB[j].y);
        }
    }

    int row0 = mb * 16 + r;
    float b0 = 0.f, b1 = 0.f;
    if (!ADDMODE || ky == 0) { b0 = bias[row0]; b1 = bias[row0 + 8]; }
    float* base0 = C + ((size_t)nb * M + row0) * L;
    float* base1 = base0 + 8 * L;
#pragma unroll
    for (int j = 0; j < 4; j++) {
        int col = (cb0 + j) * 8 + cq * 2;
        float v00 = acc[j][0] + b0;
        float v01 = acc[j][1] + b0;
        float v10 = acc[j][2] + b1;
        float v11 = acc[j][3] + b1;
        if (ADDMODE) {
            atomicAdd(base0 + col,     v00);
            atomicAdd(base0 + col + 1, v01);
            atomicAdd(base1 + col,     v10);
            atomicAdd(base1 + col + 1, v11);
        } else {
            *(float2*)(base0 + col) = make_float2(v00, v01);
            *(float2*)(base1 + col) = make_float2(v10, v11);
        }
    }
}

// ============================================================
// Convert fp32 qkv -> fp16 fragment-friendly images (attention).
// ============================================================
#define NT_Q (NNH * L)
#define NT_K (NNH * L)
#define NT_V (NNH * 16 * (L / 8))

__global__ void __launch_bounds__(256) convert_kernel()
{
    const float QS = 0.35355339059327373f * 1.4426950408889634f;
    int id = blockIdx.x * 256 + threadIdx.x;

    if (id < NT_Q) {
        int nh = id / L, q = id - nh * L;
        int n = nh >> 3, h = nh & 7;
        const float* src = g_qkv + ((size_t)n * 192 + h * 24) * L + q;
        uint32_t w[4];
#pragma unroll
        for (int j = 0; j < 4; j++)
            w[j] = pack_h2(src[(size_t)(2 * j) * L] * QS,
                           src[(size_t)(2 * j + 1) * L] * QS);
        ((uint4*)g_qh)[id] = make_uint4(w[0], w[1], w[2], w[3]);
        return;
    }
    id -= NT_Q;
    if (id < NT_K) {
        int nh = id / L, k = id - nh * L;
        int n = nh >> 3, h = nh & 7;
        const float* src = g_qkv + ((size_t)n * 192 + h * 24 + 8) * L + k;
        uint32_t w[4];
#pragma unroll
        for (int j = 0; j < 4; j++)
            w[j] = pack_h2(src[(size_t)(2 * j) * L], src[(size_t)(2 * j + 1) * L]);
        ((uint4*)g_kh)[id] = make_uint4(w[0], w[1], w[2], w[3]);
        return;
    }
    id -= NT_K;
    if (id < NT_V) {
        int nh = id / (16 * (L / 8));
        int rem = id - nh * 16 * (L / 8);
        int dim = rem / (L / 8);
        int blk = rem - dim * (L / 8);
        uint4 out;
        if (dim < 8) {
            int n = nh >> 3, h = nh & 7;
            const float* src = g_qkv + ((size_t)n * 192 + h * 24 + 16 + dim) * L + blk * 8;
            float4 f0 = *(const float4*)src;
            float4 f1 = *(const float4*)(src + 4);
            out = make_uint4(pack_h2(f0.x, f0.y), pack_h2(f0.z, f0.w),
                             pack_h2(f1.x, f1.y), pack_h2(f1.z, f1.w));
        } else if (dim == 8) {
            out = make_uint4(0x3C003C00u, 0x3C003C00u, 0x3C003C00u, 0x3C003C00u);
        } else {
            out = make_uint4(0, 0, 0, 0);
        }
        ((uint4*)g_vh)[(size_t)(nh * 16 + dim) * (L / 8) + blk] = out;
    }
}

// ============================================================
// Attention via HMMA (f16 in, f32 accum).
// ============================================================
__global__ void __launch_bounds__(256) attn_hmma_kernel()
{
    __shared__ uint32_t sK[2][512];
    __shared__ uint32_t sV[2][16 * 68];
    int t = threadIdx.x, wid = t >> 5, lane = t & 31;
    int bid = blockIdx.x;
    int qt = bid % NQT;
    int nh = bid / NQT;
    int r = lane >> 2, cq = lane & 3;

    const uint32_t* kg = (const uint32_t*)g_kh + (size_t)nh * L * 4;
    const uint32_t* vg = (const uint32_t*)g_vh + (size_t)nh * 16 * (L / 2);

    int q0 = qt * 128 + wid * 16;
    const uint32_t* qgp = (const uint32_t*)g_qh + (size_t)(nh * L + q0) * 4;
    uint32_t qa0 = qgp[r * 4 + cq];
    uint32_t qa1 = qgp[(r + 8) * 4 + cq];
    const uint32_t C15 = 0x4B804B80u;

    int pl = t >> 4, qw = t & 15;

    uint2 kreg = ((const uint2*)kg)[t];
    uint4 vreg = *(const uint4*)(vg + (size_t)pl * (L / 2) + qw * 4);
    ((uint2*)sK[0])[t] = kreg;
    *(uint4*)&sV[0][pl * 68 + qw * 4] = vreg;
    __syncthreads();

    float o0[4] = {0.f, 0.f, 0.f, 0.f};
    float o1[4] = {0.f, 0.f, 0.f, 0.f};

    for (int c = 0; c < NCHUNK; c++) {
        int cur = c & 1;
        if (c + 1 < NCHUNK) {
            kreg = ((const uint2*)(kg + (size_t)(c + 1) * 512))[t];
            vreg = *(const uint4*)(vg + (size_t)pl * (L / 2) + (c + 1) * 64 + qw * 4);
        }

        uint32_t pa[16], pb[16];
#pragma unroll
        for (int j = 0; j < 16; j++) {
            uint32_t kb = sK[cur][j * 32 + r * 4 + cq];
            float s0 = -9.f, s1 = -9.f, s2 = -9.f, s3 = -9.f;
            HMMA8(s0, s1, s2, s3, qa0, qa1, kb);
            uint32_t x, y;
            asm("cvt.rn.f16x2.f32 %0, %1, %2;" : "=r"(x) : "f"(s1), "f"(s0));
            asm("min.f16x2 %0, %0, %1;" : "+r"(x) : "r"(C15));
            asm("ex2.approx.f16x2 %0, %1;" : "=r"(x) : "r"(x));
            asm("cvt.rn.f16x2.f32 %0, %1, %2;" : "=r"(y) : "f"(s3), "f"(s2));
            asm("min.f16x2 %0, %0, %1;" : "+r"(y) : "r"(C15));
            asm("ex2.approx.f16x2 %0, %1;" : "=r"(y) : "r"(y));
            pa[j] = x;
            pb[j] = y;
        }

#pragma unroll
        for (int s = 0; s < 8; s++) {
            uint32_t b0 = sV[cur][r * 68 + s * 8 + cq];
            uint32_t b1 = sV[cur][r * 68 + s * 8 + cq + 4];
            HMMA16(o0[0], o0[1], o0[2], o0[3],
                   pa[2 * s], pb[2 * s], pa[2 * s + 1], pb[2 * s + 1], b0, b1);
            uint32_t b2 = sV[cur][(r + 8) * 68 + s * 8 + cq];
            uint32_t b3 = sV[cur][(r + 8) * 68 + s * 8 + cq + 4];
            HMMA16(o1[0], o1[1], o1[2], o1[3],
                   pa[2 * s], pb[2 * s], pa[2 * s + 1], pb[2 * s + 1], b2, b3);
        }

        if (c + 1 < NCHUNK) {
            int nxt = cur ^ 1;
            ((uint2*)sK[nxt])[t] = kreg;
            *(uint4*)&sV[nxt][pl * 68 + qw * 4] = vreg;
        }
        __syncthreads();
    }

    float ss_lo = __shfl_sync(0xffffffffu, o1[0], lane & ~3);
    float ss_hi = __shfl_sync(0xffffffffu, o1[2], lane & ~3);
    float inv_lo = 1.f / fmaxf(ss_lo, 1e-30f);
    float inv_hi = 1.f / fmaxf(ss_hi, 1e-30f);

    int n = nh >> 3, h = nh & 7;
    float* dst = g_o + ((size_t)n * HCH + h * 8 + cq * 2) * L + q0 + r;
    dst[0]     = o0[0] * inv_lo;
    dst[8]     = o0[2] * inv_hi;
    dst[L]     = o0[1] * inv_lo;
    dst[L + 8] = o0[3] * inv_hi;
}

// ============================================================
extern "C" void kernel_launch(void* const* d_in, const int* in_sizes, int n_in,
                              void* d_out, int out_size)
{
    const float* x     = (const float*)d_in[0];
    const float* qkv_w = (const float*)d_in[1];
    const float* qkv_b = (const float*)d_in[2];
    const float* pos_w = (const float*)d_in[3];
    const float* pos_b = (const float*)d_in[4];
    const float* res_w = (const float*)d_in[5];
    const float* res_b = (const float*)d_in[6];
    float* out = (float*)d_out;

    float* qkv_ptr = nullptr;
    float* o_ptr   = nullptr;
    cudaGetSymbolAddress((void**)&qkv_ptr, g_qkv);
    cudaGetSymbolAddress((void**)&o_ptr, g_o);
    uint4 *qwf, *rwf, *pwf, *of;
    uint2 *xf2, *pf2;
    cudaGetSymbolAddress((void**)&qwf, g_qwf);
    cudaGetSymbolAddress((void**)&rwf, g_rwf);
    cudaGetSymbolAddress((void**)&pwf, g_pwf);
    cudaGetSymbolAddress((void**)&of, g_of);
    cudaGetSymbolAddress((void**)&xf2, g_xf2);
    cudaGetSymbolAddress((void**)&pf2, g_pf2);

    // K0: zero g_qkv (atomicAdd target for K-split qkv GEMM)
    cudaMemsetAsync(qkv_ptr, 0, (size_t)NBATCH * 192 * L * sizeof(float));

    // K1a: build A-frags (qkv_w 192x512, res_w 512x64, pos_w 64x576)
    afrag_split_kernel<<<48, 256>>>(qkv_w, qwf, 512, 32, 12 * 32 * 32);
    afrag_split_kernel<<<16, 256>>>(res_w, rwf, 64, 4, 32 * 4 * 32);
    afrag_split_kernel<<<18, 256>>>(pos_w, pwf, 576, 36, 4 * 36 * 32);
    // K1b: build hi-only B-frags for x
    {
        int total = NBATCH * NCB * 32 * 32;
        bfrag_hi_kernel<<<(total + 255) / 256, 256>>>(x, xf2, 512, 32, total);
    }
    // K1c: qkv GEMM (split-A x f16-B HMMA, K-split 2x, atomicAdd) -> g_qkv
    hgemm_bhi_kernel<32, 2, 1><<<dim3(36, 6, NBATCH), 256>>>(
        qwf, xf2, qkv_b, qkv_ptr, 192);

    // K2: attention fragment images
    {
        int total = NT_Q + NT_K + NT_V;
        convert_kernel<<<(total + 255) / 256, 256>>>();
    }

    // K3: attention (HMMA tensor cores) -> g_o
    attn_hmma_kernel<<<NNH * NQT, 256>>>();

    // K4a: build hi-only pos im2col B-frags from V
    {
        int total = NBATCH * NCB * 36 * 32;
        pfrag_hi_kernel<<<(total + 255) / 256, 256>>>(total);
    }
    // K4b: pos conv GEMM (split-A x f16-B, K-split 4x, atomicAdd into g_o)
    hgemm_bhi_kernel<36, 4, 1><<<dim3(36, 4, NBATCH), 256>>>(
        pwf, pf2, pos_b, o_ptr, 64);

    // K5a: build full-split B-frags for attention+pos output
    {
        int total = NBATCH * NCB * 4 * 32;
        bfrag_split_kernel<<<(total + 255) / 256, 256>>>(o_ptr, of, 64, 4, total);
    }
    // K5b: res GEMM (full split-f16 HMMA) -> out
    hgemm_split_kernel<4, 1, 0><<<dim3(36, 8, NBATCH), 256>>>(
        rwf, of, res_b, out, 512);
}